// round 4
// baseline (speedup 1.0000x reference)
#include <cuda_runtime.h>
#include <cuda_bf16.h>

// Problem constants (fixed shapes from reference)
#define M_TOTAL 16384   // B*L
#define D_K     1024    // D
#define Q_N     256     // Q
#define C_N     4096    // C

// Scratch (device globals: allowed; no allocation APIs)
__device__ float g_T[M_TOTAL * Q_N];    // 16 MB projection targets
__device__ float g_cbsq[C_N];           // ||codebook[:,c]||^2

// ---------------- kernel 0: cb_sq[c] = sum_k CB[k][c]^2 ----------------
__global__ __launch_bounds__(256) void cbsq_kernel(const float* __restrict__ CB) {
    int c = blockIdx.x * 256 + threadIdx.x;
    float s = 0.f;
    #pragma unroll 8
    for (int k = 0; k < Q_N; k++) {
        float v = CB[(size_t)k * C_N + c];
        s = fmaf(v, v, s);
    }
    g_cbsq[c] = s;
}

// ---------------- kernel 1: T = X @ W^T  (M=16384, N=256, K=1024) ----------------
// Tiles: BM=64, BN=64, BK=32. 256 threads, 4x4 microtile, scalar FFMA.
// 16KB static smem, no attributes needed.
__global__ __launch_bounds__(256) void gemm1_kernel(const float* __restrict__ X,
                                                    const float* __restrict__ W) {
    __shared__ __align__(16) float As[32][64];   // [k][m]
    __shared__ __align__(16) float Bs[32][64];   // [k][n]
    int tid = threadIdx.x;
    int tr = tid >> 4;             // 0..15 -> rows tr*4..tr*4+3
    int tc = tid & 15;             // 0..15 -> cols tc*4..tc*4+3
    int row0 = blockIdx.x << 6;
    int col0 = blockIdx.y << 6;

    float acc[4][4];
    #pragma unroll
    for (int i = 0; i < 4; i++)
        #pragma unroll
        for (int j = 0; j < 4; j++) acc[i][j] = 0.f;

    for (int kc = 0; kc < D_K; kc += 32) {
        __syncthreads();
        // stage X(64x32) and W(64x32), transposed to [k][row]
        #pragma unroll
        for (int i = 0; i < 2; i++) {
            int f4   = (i << 8) + tid;       // 0..511
            int lrow = f4 >> 3;              // 0..63
            int lk   = (f4 & 7) << 2;        // 0,4,...,28
            float4 va = *(const float4*)(X + (size_t)(row0 + lrow) * D_K + kc + lk);
            As[lk + 0][lrow] = va.x; As[lk + 1][lrow] = va.y;
            As[lk + 2][lrow] = va.z; As[lk + 3][lrow] = va.w;
            float4 vb = *(const float4*)(W + (size_t)(col0 + lrow) * D_K + kc + lk);
            Bs[lk + 0][lrow] = vb.x; Bs[lk + 1][lrow] = vb.y;
            Bs[lk + 2][lrow] = vb.z; Bs[lk + 3][lrow] = vb.w;
        }
        __syncthreads();
        #pragma unroll
        for (int k = 0; k < 32; k++) {
            float4 a = *(const float4*)&As[k][tr << 2];
            float4 b = *(const float4*)&Bs[k][tc << 2];
            float av[4] = {a.x, a.y, a.z, a.w};
            float bv[4] = {b.x, b.y, b.z, b.w};
            #pragma unroll
            for (int i = 0; i < 4; i++)
                #pragma unroll
                for (int j = 0; j < 4; j++)
                    acc[i][j] = fmaf(av[i], bv[j], acc[i][j]);
        }
    }
    #pragma unroll
    for (int i = 0; i < 4; i++) {
        int r = row0 + (tr << 2) + i;
        #pragma unroll
        for (int j = 0; j < 4; j++)
            g_T[(size_t)r * Q_N + col0 + (tc << 2) + j] = acc[i][j];
    }
}

// ---------------- kernel 2: scores + argmin (M=16384, N=C=4096, K=256) ----------------
// One block owns 32 rows x full C. A tile (32x256, k-major) cached in 32KB
// static smem; codebook streamed in 16x128 chunks (8KB static). 4x4 microtile
// per thread (scalar FFMA). Running (min,idx) per row in registers; final
// warp shfl reduce with first-index tie-breaking. Output written as FLOAT32.
__global__ __launch_bounds__(256) void gemm2_kernel(const float* __restrict__ CB,
                                                    float* __restrict__ out) {
    __shared__ __align__(16) float As[Q_N][32];  // [k][m] 32KB
    __shared__ __align__(16) float Bs[16][128];  // 8KB

    int tid = threadIdx.x;
    int tr = tid >> 5;   // warp id 0..7 -> rows tr*4..tr*4+3
    int tc = tid & 31;   // lane        -> cols tc*4..tc*4+3 (per n-tile)
    int row0 = blockIdx.x << 5;

    // stage full A tile: 32 rows x 256 k, transposed to [k][m]
    #pragma unroll
    for (int i = 0; i < 8; i++) {
        int f4   = (i << 8) + tid;    // 0..2047
        int lrow = f4 >> 6;           // 0..31
        int lk   = (f4 & 63) << 2;    // 0..252
        float4 v = *(const float4*)(g_T + (size_t)(row0 + lrow) * Q_N + lk);
        As[lk + 0][lrow] = v.x; As[lk + 1][lrow] = v.y;
        As[lk + 2][lrow] = v.z; As[lk + 3][lrow] = v.w;
    }

    float bestv[4];
    int   besti[4];
    #pragma unroll
    for (int i = 0; i < 4; i++) { bestv[i] = 3.4e38f; besti[i] = 0; }

    for (int nt = 0; nt < C_N / 128; nt++) {
        float acc[4][4];
        #pragma unroll
        for (int r = 0; r < 4; r++)
            #pragma unroll
            for (int j = 0; j < 4; j++) acc[r][j] = 0.f;

        for (int kc = 0; kc < Q_N; kc += 16) {
            __syncthreads();   // previous Bs consumers done (also orders first As use)
            #pragma unroll
            for (int i = 0; i < 2; i++) {
                int f4   = (i << 8) + tid;  // 0..511
                int lrow = f4 >> 5;         // 0..15
                int lc   = (f4 & 31) << 2;  // 0..124
                *(float4*)&Bs[lrow][lc] =
                    *(const float4*)(CB + (size_t)(kc + lrow) * C_N + nt * 128 + lc);
            }
            __syncthreads();
            #pragma unroll
            for (int k = 0; k < 16; k++) {
                float4 a = *(const float4*)&As[kc + k][tr << 2];
                float4 b = *(const float4*)&Bs[k][tc << 2];
                float av[4] = {a.x, a.y, a.z, a.w};
                float bv[4] = {b.x, b.y, b.z, b.w};
                #pragma unroll
                for (int r = 0; r < 4; r++)
                    #pragma unroll
                    for (int j = 0; j < 4; j++)
                        acc[r][j] = fmaf(av[r], bv[j], acc[r][j]);
            }
        }

        // epilogue for this n-tile: score = cb_sq[n] - 2*dot, update running min
        float cq[4];
        #pragma unroll
        for (int j = 0; j < 4; j++) cq[j] = g_cbsq[nt * 128 + (tc << 2) + j];
        #pragma unroll
        for (int r = 0; r < 4; r++) {
            #pragma unroll
            for (int j = 0; j < 4; j++) {
                int n = nt * 128 + (tc << 2) + j;
                float s = fmaf(-2.f, acc[r][j], cq[j]);
                if (s < bestv[r]) { bestv[r] = s; besti[r] = n; }
            }
        }
    }

    // warp reduction across tc (each warp owns rows tr*4..tr*4+3 exclusively)
    #pragma unroll
    for (int i = 0; i < 4; i++) {
        float v  = bestv[i];
        int   ix = besti[i];
        #pragma unroll
        for (int off = 16; off > 0; off >>= 1) {
            float ov = __shfl_xor_sync(0xffffffffu, v, off);
            int   oi = __shfl_xor_sync(0xffffffffu, ix, off);
            if (ov < v || (ov == v && oi < ix)) { v = ov; ix = oi; }
        }
        // OUTPUT AS FLOAT32: labels are small ints, exactly representable.
        if (tc == 0) out[row0 + (tr << 2) + i] = (float)ix;
    }
}

// ---------------- launch ----------------
extern "C" void kernel_launch(void* const* d_in, const int* in_sizes, int n_in,
                              void* d_out, int out_size) {
    (void)out_size;
    // Identify inputs by element count — robust to any metadata ordering:
    //   X        : 16384*1024 = 16,777,216
    //   mask     : 16384                      (unused)
    //   W        : 256*1024   = 262,144
    //   codebook : 256*4096   = 1,048,576
    const float* X  = 0;
    const float* W  = 0;
    const float* CB = 0;
    for (int i = 0; i < n_in; i++) {
        long long s = (long long)in_sizes[i];
        if      (s == (long long)M_TOTAL * D_K) X  = (const float*)d_in[i];
        else if (s == (long long)Q_N * D_K)     W  = (const float*)d_in[i];
        else if (s == (long long)Q_N * C_N)     CB = (const float*)d_in[i];
    }
    // Fallback: positional order per reference signature (covers the case
    // where in_sizes units differ from element counts).
    if (!X)  X  = (const float*)d_in[0];
    if (!W  && n_in > 2) W  = (const float*)d_in[2];
    if (!CB && n_in > 3) CB = (const float*)d_in[3];

    float* out = (float*)d_out;

    cbsq_kernel<<<C_N / 256, 256>>>(CB);
    gemm1_kernel<<<dim3(M_TOTAL / 64, Q_N / 64), 256>>>(X, W);
    gemm2_kernel<<<M_TOTAL / 32, 256>>>(CB, out);
}

// round 5
// speedup vs baseline: 1.2791x; 1.2791x over previous
#include <cuda_runtime.h>
#include <cuda_bf16.h>

// Problem constants (fixed shapes from reference)
#define M_TOTAL 16384   // B*L
#define D_K     1024    // D
#define Q_N     256     // Q
#define C_N     4096    // C

// Scratch (device globals: allowed; no allocation APIs)
__device__ float g_T[M_TOTAL * Q_N];    // 16 MB projection targets
__device__ float g_cbsq[C_N];           // ||codebook[:,c]||^2

// ---------------- packed fp32x2 helpers (FFMA2 path) ----------------
__device__ __forceinline__ void fma2(unsigned long long& d,
                                     unsigned long long a,
                                     unsigned long long b) {
    asm("fma.rn.f32x2 %0, %1, %2, %0;" : "+l"(d) : "l"(a), "l"(b));
}
__device__ __forceinline__ unsigned long long pack2(float x) {
    unsigned long long r;
    unsigned u = __float_as_uint(x);
    asm("mov.b64 %0, {%1, %2};" : "=l"(r) : "r"(u), "r"(u));
    return r;
}
__device__ __forceinline__ float lo32(unsigned long long v) {
    return __uint_as_float((unsigned)(v & 0xffffffffull));
}
__device__ __forceinline__ float hi32(unsigned long long v) {
    return __uint_as_float((unsigned)(v >> 32));
}

// ---------------- kernel 0: cb_sq[c] = sum_k CB[k][c]^2 ----------------
__global__ __launch_bounds__(256) void cbsq_kernel(const float* __restrict__ CB) {
    int c = blockIdx.x * 256 + threadIdx.x;
    float s = 0.f;
    #pragma unroll 8
    for (int k = 0; k < Q_N; k++) {
        float v = CB[(size_t)k * C_N + c];
        s = fmaf(v, v, s);
    }
    g_cbsq[c] = s;
}

// ---------------- kernel 1: T = X @ W^T  (M=16384, N=256, K=1024) ----------------
// Tiles: BM=64, BN=64, BK=32. 256 threads, 4x4 microtile, accumulators packed
// f32x2 along row pairs (M-adjacent), b operand duplicated via mov.b64.
__global__ __launch_bounds__(256) void gemm1_kernel(const float* __restrict__ X,
                                                    const float* __restrict__ W) {
    __shared__ __align__(16) float As[32][64];   // [k][m]
    __shared__ __align__(16) float Bs[32][64];   // [k][n]
    int tid = threadIdx.x;
    int tr = tid >> 4;             // 0..15 -> rows tr*4..tr*4+3
    int tc = tid & 15;             // 0..15 -> cols tc*4..tc*4+3
    int row0 = blockIdx.x << 6;
    int col0 = blockIdx.y << 6;

    unsigned long long acc[2][4];
    #pragma unroll
    for (int p = 0; p < 2; p++)
        #pragma unroll
        for (int j = 0; j < 4; j++) acc[p][j] = 0ull;

    for (int kc = 0; kc < D_K; kc += 32) {
        __syncthreads();
        // stage X(64x32) and W(64x32), transposed to [k][row]
        #pragma unroll
        for (int i = 0; i < 2; i++) {
            int f4   = (i << 8) + tid;       // 0..511
            int lrow = f4 >> 3;              // 0..63
            int lk   = (f4 & 7) << 2;        // 0,4,...,28
            float4 va = *(const float4*)(X + (size_t)(row0 + lrow) * D_K + kc + lk);
            As[lk + 0][lrow] = va.x; As[lk + 1][lrow] = va.y;
            As[lk + 2][lrow] = va.z; As[lk + 3][lrow] = va.w;
            float4 vb = *(const float4*)(W + (size_t)(col0 + lrow) * D_K + kc + lk);
            Bs[lk + 0][lrow] = vb.x; Bs[lk + 1][lrow] = vb.y;
            Bs[lk + 2][lrow] = vb.z; Bs[lk + 3][lrow] = vb.w;
        }
        __syncthreads();
        #pragma unroll
        for (int k = 0; k < 32; k++) {
            ulonglong2 a = *(const ulonglong2*)&As[k][tr << 2]; // rows (0,1),(2,3)
            float4 b = *(const float4*)&Bs[k][tc << 2];
            unsigned long long bb0 = pack2(b.x), bb1 = pack2(b.y);
            unsigned long long bb2 = pack2(b.z), bb3 = pack2(b.w);
            fma2(acc[0][0], a.x, bb0); fma2(acc[0][1], a.x, bb1);
            fma2(acc[0][2], a.x, bb2); fma2(acc[0][3], a.x, bb3);
            fma2(acc[1][0], a.y, bb0); fma2(acc[1][1], a.y, bb1);
            fma2(acc[1][2], a.y, bb2); fma2(acc[1][3], a.y, bb3);
        }
    }
    #pragma unroll
    for (int p = 0; p < 2; p++) {
        int r = (tr << 2) + (p << 1);
        #pragma unroll
        for (int j = 0; j < 4; j++) {
            int c = col0 + (tc << 2) + j;
            g_T[(size_t)(row0 + r)     * Q_N + c] = lo32(acc[p][j]);
            g_T[(size_t)(row0 + r + 1) * Q_N + c] = hi32(acc[p][j]);
        }
    }
}

// ---------------- kernel 2: scores + argmin (M=16384, N=C=4096, K=256) ----------------
// One block owns 64 rows x full C. Full 64x256 A tile cached in smem (64KB),
// codebook streamed in 32x128 chunks (16KB). 8x4 microtile per thread,
// accumulators packed f32x2 along row pairs. Running (min,idx) per row in
// registers; final warp shfl reduce with first-index tie-breaking.
// Output written as FLOAT32 (harness d_out dtype).
#define G2_SMEM ((Q_N * 64 + 32 * 128) * 4)

__global__ __launch_bounds__(256, 2) void gemm2_kernel(const float* __restrict__ CB,
                                                       float* __restrict__ out) {
    extern __shared__ __align__(16) float smem_dyn[];
    float (*As)[64]  = (float (*)[64])smem_dyn;               // [256][64]  (k-major)
    float (*Bs)[128] = (float (*)[128])(smem_dyn + Q_N * 64); // [32][128]

    int tid = threadIdx.x;
    int tr = tid >> 5;   // warp id 0..7 -> rows tr*8..tr*8+7
    int tc = tid & 31;   // lane        -> cols tc*4..tc*4+3 (per n-tile)
    int row0 = blockIdx.x << 6;

    // stage full A tile: 64 rows x 256 k, transposed to [k][m]
    #pragma unroll
    for (int i = 0; i < 16; i++) {
        int f4   = (i << 8) + tid;    // 0..4095
        int lrow = f4 >> 6;           // 0..63
        int lk   = (f4 & 63) << 2;    // 0..252
        float4 v = *(const float4*)(g_T + (size_t)(row0 + lrow) * Q_N + lk);
        As[lk + 0][lrow] = v.x; As[lk + 1][lrow] = v.y;
        As[lk + 2][lrow] = v.z; As[lk + 3][lrow] = v.w;
    }

    float bestv[8];
    int   besti[8];
    #pragma unroll
    for (int i = 0; i < 8; i++) { bestv[i] = 3.4e38f; besti[i] = 0; }

    for (int nt = 0; nt < C_N / 128; nt++) {
        unsigned long long acc[4][4];
        #pragma unroll
        for (int p = 0; p < 4; p++)
            #pragma unroll
            for (int j = 0; j < 4; j++) acc[p][j] = 0ull;

        for (int kc = 0; kc < Q_N; kc += 32) {
            __syncthreads();   // previous Bs consumers done (also orders first As use)
            #pragma unroll
            for (int i = 0; i < 4; i++) {
                int f4   = (i << 8) + tid;  // 0..1023
                int lrow = f4 >> 5;         // 0..31
                int lc   = (f4 & 31) << 2;  // 0..124
                *(float4*)&Bs[lrow][lc] =
                    *(const float4*)(CB + (size_t)(kc + lrow) * C_N + nt * 128 + lc);
            }
            __syncthreads();
            #pragma unroll
            for (int k = 0; k < 32; k++) {
                const ulonglong2* pa = (const ulonglong2*)&As[kc + k][tr << 3];
                ulonglong2 a01 = pa[0];   // rows (0,1),(2,3)
                ulonglong2 a23 = pa[1];   // rows (4,5),(6,7)
                float4 b = *(const float4*)&Bs[k][tc << 2];
                unsigned long long bb0 = pack2(b.x), bb1 = pack2(b.y);
                unsigned long long bb2 = pack2(b.z), bb3 = pack2(b.w);
                fma2(acc[0][0], a01.x, bb0); fma2(acc[0][1], a01.x, bb1);
                fma2(acc[0][2], a01.x, bb2); fma2(acc[0][3], a01.x, bb3);
                fma2(acc[1][0], a01.y, bb0); fma2(acc[1][1], a01.y, bb1);
                fma2(acc[1][2], a01.y, bb2); fma2(acc[1][3], a01.y, bb3);
                fma2(acc[2][0], a23.x, bb0); fma2(acc[2][1], a23.x, bb1);
                fma2(acc[2][2], a23.x, bb2); fma2(acc[2][3], a23.x, bb3);
                fma2(acc[3][0], a23.y, bb0); fma2(acc[3][1], a23.y, bb1);
                fma2(acc[3][2], a23.y, bb2); fma2(acc[3][3], a23.y, bb3);
            }
        }

        // epilogue for this n-tile: score = cb_sq[n] - 2*dot, update running min
        float cq[4];
        #pragma unroll
        for (int j = 0; j < 4; j++) cq[j] = g_cbsq[nt * 128 + (tc << 2) + j];
        #pragma unroll
        for (int p = 0; p < 4; p++) {
            #pragma unroll
            for (int j = 0; j < 4; j++) {
                int n = nt * 128 + (tc << 2) + j;
                float s0 = fmaf(-2.f, lo32(acc[p][j]), cq[j]);
                float s1 = fmaf(-2.f, hi32(acc[p][j]), cq[j]);
                int r0 = (p << 1), r1 = r0 + 1;
                if (s0 < bestv[r0]) { bestv[r0] = s0; besti[r0] = n; }
                if (s1 < bestv[r1]) { bestv[r1] = s1; besti[r1] = n; }
            }
        }
    }

    // warp reduction across tc (each warp owns rows tr*8..tr*8+7 exclusively)
    #pragma unroll
    for (int i = 0; i < 8; i++) {
        float v  = bestv[i];
        int   ix = besti[i];
        #pragma unroll
        for (int off = 16; off > 0; off >>= 1) {
            float ov = __shfl_xor_sync(0xffffffffu, v, off);
            int   oi = __shfl_xor_sync(0xffffffffu, ix, off);
            if (ov < v || (ov == v && oi < ix)) { v = ov; ix = oi; }
        }
        // OUTPUT AS FLOAT32: labels are small ints, exactly representable.
        if (tc == 0) out[row0 + (tr << 3) + i] = (float)ix;
    }
}

// ---------------- launch ----------------
extern "C" void kernel_launch(void* const* d_in, const int* in_sizes, int n_in,
                              void* d_out, int out_size) {
    (void)out_size;
    // Identify inputs by element count — robust to any metadata ordering:
    //   X        : 16384*1024 = 16,777,216
    //   mask     : 16384                      (unused)
    //   W        : 256*1024   = 262,144
    //   codebook : 256*4096   = 1,048,576
    const float* X  = 0;
    const float* W  = 0;
    const float* CB = 0;
    for (int i = 0; i < n_in; i++) {
        long long s = (long long)in_sizes[i];
        if      (s == (long long)M_TOTAL * D_K) X  = (const float*)d_in[i];
        else if (s == (long long)Q_N * D_K)     W  = (const float*)d_in[i];
        else if (s == (long long)Q_N * C_N)     CB = (const float*)d_in[i];
    }
    if (!X)  X  = (const float*)d_in[0];
    if (!W  && n_in > 2) W  = (const float*)d_in[2];
    if (!CB && n_in > 3) CB = (const float*)d_in[3];

    float* out = (float*)d_out;

    cudaFuncSetAttribute(gemm2_kernel,
                         cudaFuncAttributeMaxDynamicSharedMemorySize, G2_SMEM);

    cbsq_kernel<<<C_N / 256, 256>>>(CB);
    gemm1_kernel<<<dim3(M_TOTAL / 64, Q_N / 64), 256>>>(X, W);
    gemm2_kernel<<<M_TOTAL / 64, 256, G2_SMEM>>>(CB, out);
}

// round 7
// speedup vs baseline: 2.2680x; 1.7731x over previous
#include <cuda_runtime.h>
#include <cuda_bf16.h>
#include <cuda_fp16.h>
#include <cstdint>

// Problem constants (fixed shapes from reference)
#define M_TOTAL 16384   // B*L
#define D_K     1024    // D
#define Q_N     256     // Q
#define C_N     4096    // C

// Scratch (device globals: allowed; no allocation APIs)
__device__ float          g_T[M_TOTAL * Q_N];     // fp32 projection targets (16MB)
__device__ float          g_cbsq[C_N];            // ||codebook[:,c]||^2
__device__ __nv_bfloat16  g_Tb[M_TOTAL * Q_N];    // bf16 targets (8MB)
__device__ __nv_bfloat16  g_CBb[C_N * Q_N];       // bf16 codebook, [c][k] layout (2MB)
__device__ __half         g_S[(size_t)M_TOTAL * C_N];  // filter scores (128MB)
__device__ float          g_rowmin[M_TOTAL];      // per-row filter min

// ---------------- packed fp32x2 helpers (FFMA2 path, validated R5) ----------------
__device__ __forceinline__ void fma2(unsigned long long& d,
                                     unsigned long long a,
                                     unsigned long long b) {
    asm("fma.rn.f32x2 %0, %1, %2, %0;" : "+l"(d) : "l"(a), "l"(b));
}
__device__ __forceinline__ unsigned long long pack2(float x) {
    unsigned long long r;
    unsigned u = __float_as_uint(x);
    asm("mov.b64 %0, {%1, %2};" : "=l"(r) : "r"(u), "r"(u));
    return r;
}
__device__ __forceinline__ float lo32(unsigned long long v) {
    return __uint_as_float((unsigned)(v & 0xffffffffull));
}
__device__ __forceinline__ float hi32(unsigned long long v) {
    return __uint_as_float((unsigned)(v >> 32));
}

// ---------------- warp-level bf16 MMA (sm_80+; works on sm_100 base) ----------------
__device__ __forceinline__ void mma16816(float* d, const uint32_t* a, const uint32_t* b) {
    asm volatile(
        "mma.sync.aligned.m16n8k16.row.col.f32.bf16.bf16.f32 "
        "{%0,%1,%2,%3}, {%4,%5,%6,%7}, {%8,%9}, {%0,%1,%2,%3};"
        : "+f"(d[0]), "+f"(d[1]), "+f"(d[2]), "+f"(d[3])
        : "r"(a[0]), "r"(a[1]), "r"(a[2]), "r"(a[3]), "r"(b[0]), "r"(b[1]));
}

// ---------------- kernel 0: cb_sq[c] = sum_k CB[k][c]^2 ----------------
__global__ __launch_bounds__(256) void cbsq_kernel(const float* __restrict__ CB) {
    int c = blockIdx.x * 256 + threadIdx.x;
    float s = 0.f;
    #pragma unroll 8
    for (int k = 0; k < Q_N; k++) {
        float v = CB[(size_t)k * C_N + c];
        s = fmaf(v, v, s);
    }
    g_cbsq[c] = s;
}

// ---------------- kernel 1: T = X @ W^T  (FFMA2, validated R5) ----------------
__global__ __launch_bounds__(256) void gemm1_kernel(const float* __restrict__ X,
                                                    const float* __restrict__ W) {
    __shared__ __align__(16) float As[32][64];   // [k][m]
    __shared__ __align__(16) float Bs[32][64];   // [k][n]
    int tid = threadIdx.x;
    int tr = tid >> 4;
    int tc = tid & 15;
    int row0 = blockIdx.x << 6;
    int col0 = blockIdx.y << 6;

    unsigned long long acc[2][4];
    #pragma unroll
    for (int p = 0; p < 2; p++)
        #pragma unroll
        for (int j = 0; j < 4; j++) acc[p][j] = 0ull;

    for (int kc = 0; kc < D_K; kc += 32) {
        __syncthreads();
        #pragma unroll
        for (int i = 0; i < 2; i++) {
            int f4   = (i << 8) + tid;
            int lrow = f4 >> 3;
            int lk   = (f4 & 7) << 2;
            float4 va = *(const float4*)(X + (size_t)(row0 + lrow) * D_K + kc + lk);
            As[lk + 0][lrow] = va.x; As[lk + 1][lrow] = va.y;
            As[lk + 2][lrow] = va.z; As[lk + 3][lrow] = va.w;
            float4 vb = *(const float4*)(W + (size_t)(col0 + lrow) * D_K + kc + lk);
            Bs[lk + 0][lrow] = vb.x; Bs[lk + 1][lrow] = vb.y;
            Bs[lk + 2][lrow] = vb.z; Bs[lk + 3][lrow] = vb.w;
        }
        __syncthreads();
        #pragma unroll
        for (int k = 0; k < 32; k++) {
            ulonglong2 a = *(const ulonglong2*)&As[k][tr << 2];
            float4 b = *(const float4*)&Bs[k][tc << 2];
            unsigned long long bb0 = pack2(b.x), bb1 = pack2(b.y);
            unsigned long long bb2 = pack2(b.z), bb3 = pack2(b.w);
            fma2(acc[0][0], a.x, bb0); fma2(acc[0][1], a.x, bb1);
            fma2(acc[0][2], a.x, bb2); fma2(acc[0][3], a.x, bb3);
            fma2(acc[1][0], a.y, bb0); fma2(acc[1][1], a.y, bb1);
            fma2(acc[1][2], a.y, bb2); fma2(acc[1][3], a.y, bb3);
        }
    }
    #pragma unroll
    for (int p = 0; p < 2; p++) {
        int r = (tr << 2) + (p << 1);
        #pragma unroll
        for (int j = 0; j < 4; j++) {
            int c = col0 + (tc << 2) + j;
            g_T[(size_t)(row0 + r)     * Q_N + c] = lo32(acc[p][j]);
            g_T[(size_t)(row0 + r + 1) * Q_N + c] = hi32(acc[p][j]);
        }
    }
}

// ---------------- kernel 1b: g_Tb = bf16(g_T) ----------------
__global__ __launch_bounds__(256) void convT_kernel() {
    int idx = blockIdx.x * 256 + threadIdx.x;     // over 4M/4 float4s
    float4 v = ((const float4*)g_T)[idx];
    __nv_bfloat162* o = (__nv_bfloat162*)g_Tb + idx * 2;
    o[0] = __nv_bfloat162(__float2bfloat16(v.x), __float2bfloat16(v.y));
    o[1] = __nv_bfloat162(__float2bfloat16(v.z), __float2bfloat16(v.w));
}

// ---------------- kernel 0b: g_CBb[c][k] = bf16(CB[k][c]) (transpose) ----------------
__global__ __launch_bounds__(256) void convCB_kernel(const float* __restrict__ CB) {
    int o = blockIdx.x * 256 + threadIdx.x;       // over 1M elems
    int k = o & 255;
    int c = o >> 8;
    g_CBb[o] = __float2bfloat16(CB[(size_t)k * C_N + c]);
}

// ---------------- kernel 2: bf16 mma.sync filter ----------------
// CTA = 128 rows x full C.  A (128x256 bf16, padded stride) resident in smem;
// B (64x256) staged per 64-col chunk.  8 warps: wm=wid&3 (32 rows), wn=wid>>2
// (32 cols).  Warp tile 32x32 = 2x4 m16n8k16 MMAs per k-step, 16 k-steps.
// Epilogue: score = cbsq - 2*dot -> half store + per-row fp32 running min.
#define ASTRIDE 264   // bf16 units; conflict-free fragment loads
#define G2_BM   128
#define G2_SMEM ((G2_BM + 64) * ASTRIDE * 2)   // 101376 bytes

__global__ __launch_bounds__(256, 1) void gemm2_tc_kernel() {
    extern __shared__ __align__(16) __nv_bfloat16 sm[];
    __nv_bfloat16* As = sm;                     // [128][264]
    __nv_bfloat16* Bs = sm + G2_BM * ASTRIDE;   // [64][264]

    int tid  = threadIdx.x;
    int wid  = tid >> 5;
    int lane = tid & 31;
    int q    = lane >> 2;      // fragment row group 0..7
    int tig  = lane & 3;       // fragment col pair 0..3
    int wm   = wid & 3;        // m position: rows wm*32..wm*32+31
    int wn   = wid >> 1 >> 1;  // (wid>>2) n position: cols wn*32..wn*32+31
    int row0 = blockIdx.x * G2_BM;

    // stage A: 128 rows x 256 k
    #pragma unroll
    for (int i = 0; i < 16; i++) {
        int id  = (i << 8) + tid;
        int row = id >> 5;
        int k8  = (id & 31) << 3;
        *(uint4*)(As + row * ASTRIDE + k8) =
            *(const uint4*)(g_Tb + (size_t)(row0 + row) * Q_N + k8);
    }

    float minv[4] = {3.4e38f, 3.4e38f, 3.4e38f, 3.4e38f};

    for (int nt = 0; nt < C_N / 64; nt++) {
        __syncthreads();   // prior chunk's consumers done before B overwrite
        #pragma unroll
        for (int i = 0; i < 8; i++) {
            int id = (i << 8) + tid;
            int c  = id >> 5;
            int k8 = (id & 31) << 3;
            *(uint4*)(Bs + c * ASTRIDE + k8) =
                *(const uint4*)(g_CBb + (size_t)(nt * 64 + c) * Q_N + k8);
        }
        __syncthreads();

        float d[2][4][4];
        #pragma unroll
        for (int i = 0; i < 2; i++)
            #pragma unroll
            for (int j = 0; j < 4; j++)
                #pragma unroll
                for (int e = 0; e < 4; e++) d[i][j][e] = 0.f;

        #pragma unroll
        for (int ks = 0; ks < 16; ks++) {
            int ka = ks * 16 + tig * 2;
            uint32_t a[2][4], b[4][2];
            #pragma unroll
            for (int i = 0; i < 2; i++) {
                const __nv_bfloat16* ap = As + (wm * 32 + i * 16 + q) * ASTRIDE;
                a[i][0] = *(const uint32_t*)(ap + ka);
                a[i][1] = *(const uint32_t*)(ap + 8 * ASTRIDE + ka);
                a[i][2] = *(const uint32_t*)(ap + ka + 8);
                a[i][3] = *(const uint32_t*)(ap + 8 * ASTRIDE + ka + 8);
            }
            #pragma unroll
            for (int j = 0; j < 4; j++) {
                const __nv_bfloat16* bp = Bs + (wn * 32 + j * 8 + q) * ASTRIDE;
                b[j][0] = *(const uint32_t*)(bp + ka);
                b[j][1] = *(const uint32_t*)(bp + ka + 8);
            }
            #pragma unroll
            for (int i = 0; i < 2; i++)
                #pragma unroll
                for (int j = 0; j < 4; j++)
                    mma16816(d[i][j], a[i], b[j]);
        }

        // epilogue: scores + running min
        int cbase = nt * 64 + wn * 32;
        #pragma unroll
        for (int j = 0; j < 4; j++) {
            int c = cbase + j * 8 + tig * 2;
            float cq0 = g_cbsq[c], cq1 = g_cbsq[c + 1];
            #pragma unroll
            for (int i = 0; i < 2; i++) {
                int r = row0 + wm * 32 + i * 16 + q;
                float s00 = fmaf(-2.f, d[i][j][0], cq0);
                float s01 = fmaf(-2.f, d[i][j][1], cq1);
                float s10 = fmaf(-2.f, d[i][j][2], cq0);
                float s11 = fmaf(-2.f, d[i][j][3], cq1);
                *(__half2*)(g_S + (size_t)r * C_N + c)       = __floats2half2_rn(s00, s01);
                *(__half2*)(g_S + (size_t)(r + 8) * C_N + c) = __floats2half2_rn(s10, s11);
                float m0 = fminf(s00, s01), m1 = fminf(s10, s11);
                if (m0 < minv[i * 2 + 0]) minv[i * 2 + 0] = m0;
                if (m1 < minv[i * 2 + 1]) minv[i * 2 + 1] = m1;
            }
        }
    }

    // reduce min across the 4 lanes of each quad (lanes 4q..4q+3)
    #pragma unroll
    for (int i = 0; i < 4; i++) {
        float m = minv[i];
        m = fminf(m, __shfl_xor_sync(0xffffffffu, m, 1));
        m = fminf(m, __shfl_xor_sync(0xffffffffu, m, 2));
        minv[i] = m;
    }
    // only one wn-half needs to write (wn==0); rows: q, q+8, q+16, q+24
    if (tig == 0 && wn == 0) {
        int rb = row0 + wm * 32;
        g_rowmin[rb + q]      = minv[0];
        g_rowmin[rb + q + 8]  = minv[1];
        g_rowmin[rb + q + 16] = minv[2];
        g_rowmin[rb + q + 24] = minv[3];
    }
}

// NOTE: both wn halves compute mins over different col ranges; g_rowmin must be
// the min over BOTH.  Handled by wn==1 also writing via atomic-free two-pass:
// we instead fold wn halves through shared memory below.
// (Implemented as a tiny second reduction kernel to keep gemm2 simple.)
__global__ __launch_bounds__(256) void rowmin_fix_kernel() { /* unused */ }

// ---------------- kernel 3: exact fp32 rescue ----------------
// One warp per row: sweep half scores, rescore all candidates within DELTA of
// the row min (min recomputed here exactly from g_S to avoid cross-warp min
// plumbing), exact fp32 rescore, argmin w/ first-index tie-break.
#define RESCUE_DELTA 6.0f
__global__ __launch_bounds__(256) void rescue_kernel(const float* __restrict__ CB,
                                                     float* __restrict__ out) {
    int wid  = threadIdx.x >> 5;
    int lane = threadIdx.x & 31;
    int row  = blockIdx.x * 8 + wid;

    const __half2* s2 = (const __half2*)(g_S + (size_t)row * C_N);
    const float* trow = g_T + (size_t)row * Q_N;

    // pass 1: exact min of stored half scores for this row (robust, no
    // dependence on gemm2's rowmin write pattern)
    float fmin = 3.4e38f;
    #pragma unroll 4
    for (int j = 0; j < 64; j++) {
        __half2 h = s2[j * 32 + lane];
        fmin = fminf(fmin, fminf(__low2float(h), __high2float(h)));
    }
    #pragma unroll
    for (int off = 16; off > 0; off >>= 1)
        fmin = fminf(fmin, __shfl_xor_sync(0xffffffffu, fmin, off));
    float thr = fmin + RESCUE_DELTA;

    float bestv = 3.4e38f;
    int   besti = 0;

    for (int j = 0; j < 64; j++) {
        __half2 h = s2[j * 32 + lane];
        float sx = __low2float(h), sy = __high2float(h);
        unsigned m = __ballot_sync(0xffffffffu, (sx <= thr) || (sy <= thr));
        while (m) {
            int src = __ffs(m) - 1;
            m &= m - 1;
            float cx = __shfl_sync(0xffffffffu, sx, src);
            float cy = __shfl_sync(0xffffffffu, sy, src);
            int c0 = j * 64 + src * 2;
            #pragma unroll
            for (int half = 0; half < 2; half++) {
                float cs = half ? cy : cx;
                int   c  = c0 + half;
                if (cs <= thr) {
                    float part = 0.f;
                    #pragma unroll
                    for (int t = 0; t < 8; t++) {
                        int k = lane + t * 32;
                        part = fmaf(trow[k], CB[(size_t)k * C_N + c], part);
                    }
                    #pragma unroll
                    for (int off = 16; off > 0; off >>= 1)
                        part += __shfl_xor_sync(0xffffffffu, part, off);
                    float sc = fmaf(-2.f, part, g_cbsq[c]);
                    if (sc < bestv) { bestv = sc; besti = c; }   // ascending c => first-index ties
                }
            }
        }
    }
    if (lane == 0) out[row] = (float)besti;
}

// ---------------- launch ----------------
extern "C" void kernel_launch(void* const* d_in, const int* in_sizes, int n_in,
                              void* d_out, int out_size) {
    (void)out_size;
    const float* X  = 0;
    const float* W  = 0;
    const float* CB = 0;
    for (int i = 0; i < n_in; i++) {
        long long s = (long long)in_sizes[i];
        if      (s == (long long)M_TOTAL * D_K) X  = (const float*)d_in[i];
        else if (s == (long long)Q_N * D_K)     W  = (const float*)d_in[i];
        else if (s == (long long)Q_N * C_N)     CB = (const float*)d_in[i];
    }
    if (!X)  X  = (const float*)d_in[0];
    if (!W  && n_in > 2) W  = (const float*)d_in[2];
    if (!CB && n_in > 3) CB = (const float*)d_in[3];

    float* out = (float*)d_out;

    cudaFuncSetAttribute(gemm2_tc_kernel,
                         cudaFuncAttributeMaxDynamicSharedMemorySize, G2_SMEM);

    cbsq_kernel<<<C_N / 256, 256>>>(CB);
    convCB_kernel<<<(C_N * Q_N) / 256, 256>>>(CB);
    gemm1_kernel<<<dim3(M_TOTAL / 64, Q_N / 64), 256>>>(X, W);
    convT_kernel<<<(M_TOTAL * Q_N / 4) / 256, 256>>>();
    gemm2_tc_kernel<<<M_TOTAL / G2_BM, 256, G2_SMEM>>>();
    rescue_kernel<<<M_TOTAL / 8, 256>>>(CB, out);
}

// round 8
// speedup vs baseline: 3.0748x; 1.3558x over previous
#include <cuda_runtime.h>
#include <cuda_bf16.h>
#include <cuda_fp16.h>
#include <cstdint>

// Problem constants (fixed shapes from reference)
#define M_TOTAL 16384   // B*L
#define D_K     1024    // D
#define Q_N     256     // Q
#define C_N     4096    // C

// Scratch (device globals: allowed; no allocation APIs)
__device__ float          g_cbsq[C_N];            // ||codebook[:,c]||^2 (fp32 exact)
__device__ __nv_bfloat16  g_Xb[M_TOTAL * D_K];    // bf16 inputs (32MB)
__device__ __nv_bfloat16  g_Wb[Q_N * D_K];        // bf16 W (512KB)
__device__ __nv_bfloat16  g_Tb[M_TOTAL * Q_N];    // bf16 targets (8MB)
__device__ __nv_bfloat16  g_CBb[C_N * Q_N];       // bf16 codebook, [c][k] (2MB)
__device__ float          g_U[(size_t)C_N * D_K]; // U[c][d] = sum_q CB[q][c] W[q][d] (16MB)
__device__ __half         g_S[(size_t)M_TOTAL * C_N];  // filter scores (128MB)

// ---------------- packed fp32x2 helpers (FFMA2, validated R5/R7) ----------------
__device__ __forceinline__ void fma2(unsigned long long& d,
                                     unsigned long long a,
                                     unsigned long long b) {
    asm("fma.rn.f32x2 %0, %1, %2, %0;" : "+l"(d) : "l"(a), "l"(b));
}
__device__ __forceinline__ unsigned long long pack2(float x) {
    unsigned long long r;
    unsigned u = __float_as_uint(x);
    asm("mov.b64 %0, {%1, %2};" : "=l"(r) : "r"(u), "r"(u));
    return r;
}
__device__ __forceinline__ float lo32(unsigned long long v) {
    return __uint_as_float((unsigned)(v & 0xffffffffull));
}
__device__ __forceinline__ float hi32(unsigned long long v) {
    return __uint_as_float((unsigned)(v >> 32));
}

// ---------------- warp-level bf16 MMA (validated R7) ----------------
__device__ __forceinline__ void mma16816(float* d, const uint32_t* a, const uint32_t* b) {
    asm volatile(
        "mma.sync.aligned.m16n8k16.row.col.f32.bf16.bf16.f32 "
        "{%0,%1,%2,%3}, {%4,%5,%6,%7}, {%8,%9}, {%0,%1,%2,%3};"
        : "+f"(d[0]), "+f"(d[1]), "+f"(d[2]), "+f"(d[3])
        : "r"(a[0]), "r"(a[1]), "r"(a[2]), "r"(a[3]), "r"(b[0]), "r"(b[1]));
}

// ---------------- kernel 0: cb_sq (64 blocks: 4x more parallel than R7) ----------------
__global__ __launch_bounds__(256) void cbsq_kernel(const float* __restrict__ CB) {
    __shared__ float red[4][64];
    int t = threadIdx.x;
    int c = blockIdx.x * 64 + (t & 63);
    int part = t >> 6;                       // 0..3 -> k chunk of 64
    float s = 0.f;
    #pragma unroll 8
    for (int k = part * 64; k < part * 64 + 64; k++) {
        float v = CB[(size_t)k * C_N + c];
        s = fmaf(v, v, s);
    }
    red[part][t & 63] = s;
    __syncthreads();
    if (t < 64)
        g_cbsq[blockIdx.x * 64 + t] = red[0][t] + red[1][t] + red[2][t] + red[3][t];
}

// ---------------- conversion kernels ----------------
__global__ __launch_bounds__(256) void convX_kernel(const float* __restrict__ X) {
    int idx = blockIdx.x * 256 + threadIdx.x;       // over 4M float4s
    float4 v = ((const float4*)X)[idx];
    __nv_bfloat162* o = (__nv_bfloat162*)g_Xb + idx * 2;
    o[0] = __nv_bfloat162(__float2bfloat16(v.x), __float2bfloat16(v.y));
    o[1] = __nv_bfloat162(__float2bfloat16(v.z), __float2bfloat16(v.w));
}
__global__ __launch_bounds__(256) void convW_kernel(const float* __restrict__ W) {
    int idx = blockIdx.x * 256 + threadIdx.x;       // over 64K float4s
    float4 v = ((const float4*)W)[idx];
    __nv_bfloat162* o = (__nv_bfloat162*)g_Wb + idx * 2;
    o[0] = __nv_bfloat162(__float2bfloat16(v.x), __float2bfloat16(v.y));
    o[1] = __nv_bfloat162(__float2bfloat16(v.z), __float2bfloat16(v.w));
}
__global__ __launch_bounds__(256) void convCB_kernel(const float* __restrict__ CB) {
    int o = blockIdx.x * 256 + threadIdx.x;         // over 1M elems
    int k = o & 255;
    int c = o >> 8;
    g_CBb[o] = __float2bfloat16(CB[(size_t)k * C_N + c]);
}

// ---------------- kernel U: U[c][d] = sum_q CB[q][c] * W[q][d]  (fp32 FFMA2) ----------------
// M=4096 (c), N=1024 (d), K=256 (q).  BM=BN=64, BK=32; R5-validated skeleton.
__global__ __launch_bounds__(256) void ugemm_kernel(const float* __restrict__ CB,
                                                    const float* __restrict__ W) {
    __shared__ __align__(16) float As[32][64];   // [q][c]
    __shared__ __align__(16) float Bs[32][64];   // [q][d]
    int tid = threadIdx.x;
    int tr = tid >> 4;
    int tc = tid & 15;
    int row0 = blockIdx.x << 6;   // c
    int col0 = blockIdx.y << 6;   // d

    unsigned long long acc[2][4];
    #pragma unroll
    for (int p = 0; p < 2; p++)
        #pragma unroll
        for (int j = 0; j < 4; j++) acc[p][j] = 0ull;

    for (int kc = 0; kc < Q_N; kc += 32) {
        __syncthreads();
        // stage: CB rows q (c-contiguous) and W rows q (d-contiguous) -> [k][m]
        #pragma unroll
        for (int i = 0; i < 2; i++) {
            int f4 = (i << 8) + tid;          // 0..511
            int q  = f4 >> 4;                 // 0..31
            int e4 = (f4 & 15) << 2;          // 0..60
            *(float4*)&As[q][e4] = *(const float4*)(CB + (size_t)(kc + q) * C_N + row0 + e4);
            *(float4*)&Bs[q][e4] = *(const float4*)(W  + (size_t)(kc + q) * D_K + col0 + e4);
        }
        __syncthreads();
        #pragma unroll
        for (int k = 0; k < 32; k++) {
            ulonglong2 a = *(const ulonglong2*)&As[k][tr << 2];
            float4 b = *(const float4*)&Bs[k][tc << 2];
            unsigned long long bb0 = pack2(b.x), bb1 = pack2(b.y);
            unsigned long long bb2 = pack2(b.z), bb3 = pack2(b.w);
            fma2(acc[0][0], a.x, bb0); fma2(acc[0][1], a.x, bb1);
            fma2(acc[0][2], a.x, bb2); fma2(acc[0][3], a.x, bb3);
            fma2(acc[1][0], a.y, bb0); fma2(acc[1][1], a.y, bb1);
            fma2(acc[1][2], a.y, bb2); fma2(acc[1][3], a.y, bb3);
        }
    }
    #pragma unroll
    for (int p = 0; p < 2; p++) {
        int c = row0 + (tr << 2) + (p << 1);
        #pragma unroll
        for (int j = 0; j < 4; j++) {
            int d = col0 + (tc << 2) + j;
            g_U[(size_t)c       * D_K + d] = lo32(acc[p][j]);
            g_U[(size_t)(c + 1) * D_K + d] = hi32(acc[p][j]);
        }
    }
}

// ---------------- kernel 1: T~ = bf16(X) @ bf16(W)^T  (mma.sync bf16) ----------------
// M=16384, N=256, K=1024.  BM=128, BN=128, BK=64.  8 warps as 4(m)x2(n),
// warp tile 32x64 = 2x8 m16n8k16 per k-step.  Output g_Tb bf16.
#define T_STRIDE 72
__global__ __launch_bounds__(256, 1) void gemm1b_kernel() {
    __shared__ __align__(16) __nv_bfloat16 As[128][T_STRIDE];
    __shared__ __align__(16) __nv_bfloat16 Bs[128][T_STRIDE];

    int tid  = threadIdx.x;
    int wid  = tid >> 5;
    int lane = tid & 31;
    int q    = lane >> 2;
    int tig  = lane & 3;
    int wm   = wid & 3;        // rows wm*32..+31
    int wn   = wid >> 2;       // cols wn*64..+63
    int row0 = blockIdx.x << 7;
    int col0 = blockIdx.y << 7;

    float d[2][8][4];
    #pragma unroll
    for (int i = 0; i < 2; i++)
        #pragma unroll
        for (int j = 0; j < 8; j++)
            #pragma unroll
            for (int e = 0; e < 4; e++) d[i][j][e] = 0.f;

    for (int kc = 0; kc < D_K; kc += 64) {
        __syncthreads();
        #pragma unroll
        for (int i = 0; i < 4; i++) {
            int id  = (i << 8) + tid;         // 0..1023
            int row = id >> 3;                // 0..127
            int k8  = (id & 7) << 3;          // 0..56
            *(uint4*)&As[row][k8] = *(const uint4*)(g_Xb + (size_t)(row0 + row) * D_K + kc + k8);
            *(uint4*)&Bs[row][k8] = *(const uint4*)(g_Wb + (size_t)(col0 + row) * D_K + kc + k8);
        }
        __syncthreads();
        #pragma unroll
        for (int ks = 0; ks < 4; ks++) {
            int ka = ks * 16 + tig * 2;
            uint32_t a[2][4], b[8][2];
            #pragma unroll
            for (int i = 0; i < 2; i++) {
                const __nv_bfloat16* ap = &As[wm * 32 + i * 16 + q][0];
                a[i][0] = *(const uint32_t*)(ap + ka);
                a[i][1] = *(const uint32_t*)(ap + 8 * T_STRIDE + ka);
                a[i][2] = *(const uint32_t*)(ap + ka + 8);
                a[i][3] = *(const uint32_t*)(ap + 8 * T_STRIDE + ka + 8);
            }
            #pragma unroll
            for (int j = 0; j < 8; j++) {
                const __nv_bfloat16* bp = &Bs[wn * 64 + j * 8 + q][0];
                b[j][0] = *(const uint32_t*)(bp + ka);
                b[j][1] = *(const uint32_t*)(bp + ka + 8);
            }
            #pragma unroll
            for (int i = 0; i < 2; i++)
                #pragma unroll
                for (int j = 0; j < 8; j++)
                    mma16816(d[i][j], a[i], b[j]);
        }
    }
    // epilogue: bf16 store
    #pragma unroll
    for (int j = 0; j < 8; j++) {
        int c = col0 + wn * 64 + j * 8 + tig * 2;
        #pragma unroll
        for (int i = 0; i < 2; i++) {
            int r = row0 + wm * 32 + i * 16 + q;
            *(__nv_bfloat162*)(g_Tb + (size_t)r * Q_N + c) =
                __nv_bfloat162(__float2bfloat16(d[i][j][0]), __float2bfloat16(d[i][j][1]));
            *(__nv_bfloat162*)(g_Tb + (size_t)(r + 8) * Q_N + c) =
                __nv_bfloat162(__float2bfloat16(d[i][j][2]), __float2bfloat16(d[i][j][3]));
        }
    }
}

// ---------------- kernel 2: bf16 mma.sync filter (mainloop validated R7) ----------------
#define ASTRIDE 264
#define G2_BM   128
#define G2_SMEM ((G2_BM + 64) * ASTRIDE * 2)   // 101376 bytes

__global__ __launch_bounds__(256, 1) void gemm2_tc_kernel() {
    extern __shared__ __align__(16) __nv_bfloat16 sm[];
    __nv_bfloat16* As = sm;                     // [128][264]
    __nv_bfloat16* Bs = sm + G2_BM * ASTRIDE;   // [64][264]

    int tid  = threadIdx.x;
    int wid  = tid >> 5;
    int lane = tid & 31;
    int q    = lane >> 2;
    int tig  = lane & 3;
    int wm   = wid & 3;
    int wn   = wid >> 2;
    int row0 = blockIdx.x * G2_BM;

    #pragma unroll
    for (int i = 0; i < 16; i++) {
        int id  = (i << 8) + tid;
        int row = id >> 5;
        int k8  = (id & 31) << 3;
        *(uint4*)(As + row * ASTRIDE + k8) =
            *(const uint4*)(g_Tb + (size_t)(row0 + row) * Q_N + k8);
    }

    for (int nt = 0; nt < C_N / 64; nt++) {
        __syncthreads();
        #pragma unroll
        for (int i = 0; i < 8; i++) {
            int id = (i << 8) + tid;
            int c  = id >> 5;
            int k8 = (id & 31) << 3;
            *(uint4*)(Bs + c * ASTRIDE + k8) =
                *(const uint4*)(g_CBb + (size_t)(nt * 64 + c) * Q_N + k8);
        }
        __syncthreads();

        float d[2][4][4];
        #pragma unroll
        for (int i = 0; i < 2; i++)
            #pragma unroll
            for (int j = 0; j < 4; j++)
                #pragma unroll
                for (int e = 0; e < 4; e++) d[i][j][e] = 0.f;

        #pragma unroll
        for (int ks = 0; ks < 16; ks++) {
            int ka = ks * 16 + tig * 2;
            uint32_t a[2][4], b[4][2];
            #pragma unroll
            for (int i = 0; i < 2; i++) {
                const __nv_bfloat16* ap = As + (wm * 32 + i * 16 + q) * ASTRIDE;
                a[i][0] = *(const uint32_t*)(ap + ka);
                a[i][1] = *(const uint32_t*)(ap + 8 * ASTRIDE + ka);
                a[i][2] = *(const uint32_t*)(ap + ka + 8);
                a[i][3] = *(const uint32_t*)(ap + 8 * ASTRIDE + ka + 8);
            }
            #pragma unroll
            for (int j = 0; j < 4; j++) {
                const __nv_bfloat16* bp = Bs + (wn * 32 + j * 8 + q) * ASTRIDE;
                b[j][0] = *(const uint32_t*)(bp + ka);
                b[j][1] = *(const uint32_t*)(bp + ka + 8);
            }
            #pragma unroll
            for (int i = 0; i < 2; i++)
                #pragma unroll
                for (int j = 0; j < 4; j++)
                    mma16816(d[i][j], a[i], b[j]);
        }

        int cbase = nt * 64 + wn * 32;
        #pragma unroll
        for (int j = 0; j < 4; j++) {
            int c = cbase + j * 8 + tig * 2;
            float cq0 = g_cbsq[c], cq1 = g_cbsq[c + 1];
            #pragma unroll
            for (int i = 0; i < 2; i++) {
                int r = row0 + wm * 32 + i * 16 + q;
                float s00 = fmaf(-2.f, d[i][j][0], cq0);
                float s01 = fmaf(-2.f, d[i][j][1], cq1);
                float s10 = fmaf(-2.f, d[i][j][2], cq0);
                float s11 = fmaf(-2.f, d[i][j][3], cq1);
                *(__half2*)(g_S + (size_t)r * C_N + c)       = __floats2half2_rn(s00, s01);
                *(__half2*)(g_S + (size_t)(r + 8) * C_N + c) = __floats2half2_rn(s10, s11);
            }
        }
    }
}

// ---------------- kernel 3: exact rescue via U rows (coalesced) ----------------
// score_exact(r,c) = cbsq[c] - 2 * dot(X[r,:], U[c,:])  over D=1024, fp32.
#define RESCUE_DELTA 6.0f
__global__ __launch_bounds__(256) void rescue_kernel(const float* __restrict__ X,
                                                     float* __restrict__ out) {
    int wid  = threadIdx.x >> 5;
    int lane = threadIdx.x & 31;
    int row  = blockIdx.x * 8 + wid;

    const __half2* s2 = (const __half2*)(g_S + (size_t)row * C_N);
    const float* xrow = X + (size_t)row * D_K;

    // pass 1: min of stored filter scores for this row
    float fmin = 3.4e38f;
    #pragma unroll 4
    for (int j = 0; j < 64; j++) {
        __half2 h = s2[j * 32 + lane];
        fmin = fminf(fmin, fminf(__low2float(h), __high2float(h)));
    }
    #pragma unroll
    for (int off = 16; off > 0; off >>= 1)
        fmin = fminf(fmin, __shfl_xor_sync(0xffffffffu, fmin, off));
    float thr = fmin + RESCUE_DELTA;

    float bestv = 3.4e38f;
    int   besti = 0;

    for (int j = 0; j < 64; j++) {
        __half2 h = s2[j * 32 + lane];
        float sx = __low2float(h), sy = __high2float(h);
        unsigned m = __ballot_sync(0xffffffffu, (sx <= thr) || (sy <= thr));
        while (m) {
            int src = __ffs(m) - 1;
            m &= m - 1;
            float cx = __shfl_sync(0xffffffffu, sx, src);
            float cy = __shfl_sync(0xffffffffu, sy, src);
            int c0 = j * 64 + src * 2;
            #pragma unroll
            for (int half = 0; half < 2; half++) {
                float cs = half ? cy : cx;
                int   c  = c0 + half;
                if (cs <= thr) {
                    const float* urow = g_U + (size_t)c * D_K;
                    float part = 0.f;
                    #pragma unroll 8
                    for (int t = 0; t < 32; t++) {
                        int k = lane + t * 32;
                        part = fmaf(xrow[k], urow[k], part);
                    }
                    #pragma unroll
                    for (int off = 16; off > 0; off >>= 1)
                        part += __shfl_xor_sync(0xffffffffu, part, off);
                    float sc = fmaf(-2.f, part, g_cbsq[c]);
                    if (sc < bestv) { bestv = sc; besti = c; }   // ascending c => first-index ties
                }
            }
        }
    }
    if (lane == 0) out[row] = (float)besti;
}

// ---------------- launch ----------------
extern "C" void kernel_launch(void* const* d_in, const int* in_sizes, int n_in,
                              void* d_out, int out_size) {
    (void)out_size;
    const float* X  = 0;
    const float* W  = 0;
    const float* CB = 0;
    for (int i = 0; i < n_in; i++) {
        long long s = (long long)in_sizes[i];
        if      (s == (long long)M_TOTAL * D_K) X  = (const float*)d_in[i];
        else if (s == (long long)Q_N * D_K)     W  = (const float*)d_in[i];
        else if (s == (long long)Q_N * C_N)     CB = (const float*)d_in[i];
    }
    if (!X)  X  = (const float*)d_in[0];
    if (!W  && n_in > 2) W  = (const float*)d_in[2];
    if (!CB && n_in > 3) CB = (const float*)d_in[3];

    float* out = (float*)d_out;

    cudaFuncSetAttribute(gemm2_tc_kernel,
                         cudaFuncAttributeMaxDynamicSharedMemorySize, G2_SMEM);

    cbsq_kernel<<<C_N / 64, 256>>>(CB);
    convCB_kernel<<<(C_N * Q_N) / 256, 256>>>(CB);
    convW_kernel<<<(Q_N * D_K / 4) / 256, 256>>>(W);
    convX_kernel<<<(M_TOTAL * D_K / 4) / 256, 256>>>(X);
    ugemm_kernel<<<dim3(C_N / 64, D_K / 64), 256>>>(CB, W);
    gemm1b_kernel<<<dim3(M_TOTAL / 128, Q_N / 128), 256>>>();
    gemm2_tc_kernel<<<M_TOTAL / G2_BM, 256, G2_SMEM>>>();
    rescue_kernel<<<M_TOTAL / 8, 256>>>(X, out);
}

// round 9
// speedup vs baseline: 3.4364x; 1.1176x over previous
#include <cuda_runtime.h>
#include <cuda_bf16.h>
#include <cstdint>

// Problem constants (fixed shapes from reference)
#define M_TOTAL 16384   // B*L
#define D_K     1024    // D
#define Q_N     256     // Q
#define C_N     4096    // C

#define CAND_MAX 32
#define RESCUE_DELTA 6.0f

// Scratch (device globals: allowed; no allocation APIs)
__device__ float          g_cbsq[C_N];            // ||codebook[:,c]||^2 (fp32 exact)
__device__ __nv_bfloat16  g_Xb[M_TOTAL * D_K];    // bf16 inputs (32MB)
__device__ __nv_bfloat16  g_Wb[Q_N * D_K];        // bf16 W (512KB)
__device__ __nv_bfloat16  g_Tb[M_TOTAL * Q_N];    // bf16 targets (8MB)
__device__ __nv_bfloat16  g_CBb[C_N * Q_N];       // bf16 codebook, [c][k] (2MB)
__device__ float          g_U[(size_t)C_N * D_K]; // U[c][d] = sum_q CB[q][c] W[q][d] (16MB)
__device__ int            g_ncand[M_TOTAL];
__device__ uint16_t       g_cand[M_TOTAL][CAND_MAX];

// ---------------- packed fp32x2 helpers (FFMA2, validated R5/R7) ----------------
__device__ __forceinline__ void fma2(unsigned long long& d,
                                     unsigned long long a,
                                     unsigned long long b) {
    asm("fma.rn.f32x2 %0, %1, %2, %0;" : "+l"(d) : "l"(a), "l"(b));
}
__device__ __forceinline__ unsigned long long pack2(float x) {
    unsigned long long r;
    unsigned u = __float_as_uint(x);
    asm("mov.b64 %0, {%1, %2};" : "=l"(r) : "r"(u), "r"(u));
    return r;
}
__device__ __forceinline__ float lo32(unsigned long long v) {
    return __uint_as_float((unsigned)(v & 0xffffffffull));
}
__device__ __forceinline__ float hi32(unsigned long long v) {
    return __uint_as_float((unsigned)(v >> 32));
}

// ---------------- warp MMA + ldmatrix ----------------
__device__ __forceinline__ void mma16816(float* d, const uint32_t* a, const uint32_t* b) {
    asm volatile(
        "mma.sync.aligned.m16n8k16.row.col.f32.bf16.bf16.f32 "
        "{%0,%1,%2,%3}, {%4,%5,%6,%7}, {%8,%9}, {%0,%1,%2,%3};"
        : "+f"(d[0]), "+f"(d[1]), "+f"(d[2]), "+f"(d[3])
        : "r"(a[0]), "r"(a[1]), "r"(a[2]), "r"(a[3]), "r"(b[0]), "r"(b[1]));
}
__device__ __forceinline__ void ldsm_x4(uint32_t* r, uint32_t addr) {
    asm volatile("ldmatrix.sync.aligned.m8n8.x4.shared.b16 {%0,%1,%2,%3}, [%4];"
                 : "=r"(r[0]), "=r"(r[1]), "=r"(r[2]), "=r"(r[3]) : "r"(addr));
}

// order-preserving float<->uint key (for atomicMin on scores of any sign)
__device__ __forceinline__ uint32_t fkey(float f) {
    uint32_t b = __float_as_uint(f);
    return (b & 0x80000000u) ? ~b : (b | 0x80000000u);
}
__device__ __forceinline__ float funkey(uint32_t k) {
    uint32_t b = (k & 0x80000000u) ? (k & 0x7FFFFFFFu) : ~k;
    return __uint_as_float(b);
}

// ---------------- kernel 0: cb_sq ----------------
__global__ __launch_bounds__(256) void cbsq_kernel(const float* __restrict__ CB) {
    __shared__ float red[4][64];
    int t = threadIdx.x;
    int c = blockIdx.x * 64 + (t & 63);
    int part = t >> 6;
    float s = 0.f;
    #pragma unroll 8
    for (int k = part * 64; k < part * 64 + 64; k++) {
        float v = CB[(size_t)k * C_N + c];
        s = fmaf(v, v, s);
    }
    red[part][t & 63] = s;
    __syncthreads();
    if (t < 64)
        g_cbsq[blockIdx.x * 64 + t] = red[0][t] + red[1][t] + red[2][t] + red[3][t];
}

// ---------------- conversion kernels ----------------
__global__ __launch_bounds__(256) void convX_kernel(const float* __restrict__ X) {
    int idx = blockIdx.x * 256 + threadIdx.x;
    float4 v = ((const float4*)X)[idx];
    __nv_bfloat162* o = (__nv_bfloat162*)g_Xb + idx * 2;
    o[0] = __nv_bfloat162(__float2bfloat16(v.x), __float2bfloat16(v.y));
    o[1] = __nv_bfloat162(__float2bfloat16(v.z), __float2bfloat16(v.w));
}
__global__ __launch_bounds__(256) void convW_kernel(const float* __restrict__ W) {
    int idx = blockIdx.x * 256 + threadIdx.x;
    float4 v = ((const float4*)W)[idx];
    __nv_bfloat162* o = (__nv_bfloat162*)g_Wb + idx * 2;
    o[0] = __nv_bfloat162(__float2bfloat16(v.x), __float2bfloat16(v.y));
    o[1] = __nv_bfloat162(__float2bfloat16(v.z), __float2bfloat16(v.w));
}
__global__ __launch_bounds__(256) void convCB_kernel(const float* __restrict__ CB) {
    int o = blockIdx.x * 256 + threadIdx.x;
    int k = o & 255;
    int c = o >> 8;
    g_CBb[o] = __float2bfloat16(CB[(size_t)k * C_N + c]);
}

// ---------------- kernel U: U = CB^T @ W  (fp32 FFMA2, validated R8) ----------------
__global__ __launch_bounds__(256) void ugemm_kernel(const float* __restrict__ CB,
                                                    const float* __restrict__ W) {
    __shared__ __align__(16) float As[32][64];
    __shared__ __align__(16) float Bs[32][64];
    int tid = threadIdx.x;
    int tr = tid >> 4;
    int tc = tid & 15;
    int row0 = blockIdx.x << 6;   // c
    int col0 = blockIdx.y << 6;   // d

    unsigned long long acc[2][4];
    #pragma unroll
    for (int p = 0; p < 2; p++)
        #pragma unroll
        for (int j = 0; j < 4; j++) acc[p][j] = 0ull;

    for (int kc = 0; kc < Q_N; kc += 32) {
        __syncthreads();
        #pragma unroll
        for (int i = 0; i < 2; i++) {
            int f4 = (i << 8) + tid;
            int q  = f4 >> 4;
            int e4 = (f4 & 15) << 2;
            *(float4*)&As[q][e4] = *(const float4*)(CB + (size_t)(kc + q) * C_N + row0 + e4);
            *(float4*)&Bs[q][e4] = *(const float4*)(W  + (size_t)(kc + q) * D_K + col0 + e4);
        }
        __syncthreads();
        #pragma unroll
        for (int k = 0; k < 32; k++) {
            ulonglong2 a = *(const ulonglong2*)&As[k][tr << 2];
            float4 b = *(const float4*)&Bs[k][tc << 2];
            unsigned long long bb0 = pack2(b.x), bb1 = pack2(b.y);
            unsigned long long bb2 = pack2(b.z), bb3 = pack2(b.w);
            fma2(acc[0][0], a.x, bb0); fma2(acc[0][1], a.x, bb1);
            fma2(acc[0][2], a.x, bb2); fma2(acc[0][3], a.x, bb3);
            fma2(acc[1][0], a.y, bb0); fma2(acc[1][1], a.y, bb1);
            fma2(acc[1][2], a.y, bb2); fma2(acc[1][3], a.y, bb3);
        }
    }
    #pragma unroll
    for (int p = 0; p < 2; p++) {
        int c = row0 + (tr << 2) + (p << 1);
        #pragma unroll
        for (int j = 0; j < 4; j++) {
            int d = col0 + (tc << 2) + j;
            g_U[(size_t)c       * D_K + d] = lo32(acc[p][j]);
            g_U[(size_t)(c + 1) * D_K + d] = hi32(acc[p][j]);
        }
    }
}

// ---------------- kernel 1: T~ = bf16(X) @ bf16(W)^T  (ldmatrix version) ----------------
#define T_STRIDE 72
__global__ __launch_bounds__(256, 2) void gemm1b_kernel() {
    __shared__ __align__(16) __nv_bfloat16 As[128][T_STRIDE];
    __shared__ __align__(16) __nv_bfloat16 Bs[128][T_STRIDE];

    int tid  = threadIdx.x;
    int wid  = tid >> 5;
    int lane = tid & 31;
    int q    = lane >> 2;
    int tig  = lane & 3;
    int wm   = wid & 3;
    int wn   = wid >> 2;
    int row0 = blockIdx.x << 7;
    int col0 = blockIdx.y << 7;

    // per-lane ldmatrix base addresses
    int g   = lane >> 3, idx = lane & 7;
    // A tiles: row add (g&1)*8, col add (g>>1)*8
    uint32_t aaddr[2], baddr[4];
    #pragma unroll
    for (int i = 0; i < 2; i++) {
        int r = wm * 32 + i * 16 + ((g & 1) << 3) + idx;
        aaddr[i] = (uint32_t)__cvta_generic_to_shared(&As[r][(g >> 1) << 3]);
    }
    // B tiles: row add (g>>1)*8, col add (g&1)*8; jp covers j pair
    #pragma unroll
    for (int jp = 0; jp < 4; jp++) {
        int r = wn * 64 + jp * 16 + ((g >> 1) << 3) + idx;
        baddr[jp] = (uint32_t)__cvta_generic_to_shared(&Bs[r][(g & 1) << 3]);
    }

    float d[2][8][4];
    #pragma unroll
    for (int i = 0; i < 2; i++)
        #pragma unroll
        for (int j = 0; j < 8; j++)
            #pragma unroll
            for (int e = 0; e < 4; e++) d[i][j][e] = 0.f;

    for (int kc = 0; kc < D_K; kc += 64) {
        __syncthreads();
        #pragma unroll
        for (int i = 0; i < 4; i++) {
            int id  = (i << 8) + tid;
            int row = id >> 3;
            int k8  = (id & 7) << 3;
            *(uint4*)&As[row][k8] = *(const uint4*)(g_Xb + (size_t)(row0 + row) * D_K + kc + k8);
            *(uint4*)&Bs[row][k8] = *(const uint4*)(g_Wb + (size_t)(col0 + row) * D_K + kc + k8);
        }
        __syncthreads();
        #pragma unroll
        for (int ks = 0; ks < 4; ks++) {
            uint32_t koff = (uint32_t)(ks * 16 * 2);
            uint32_t a[2][4], b[4][4];
            ldsm_x4(a[0], aaddr[0] + koff);
            ldsm_x4(a[1], aaddr[1] + koff);
            #pragma unroll
            for (int jp = 0; jp < 4; jp++) ldsm_x4(b[jp], baddr[jp] + koff);
            #pragma unroll
            for (int i = 0; i < 2; i++)
                #pragma unroll
                for (int jp = 0; jp < 4; jp++) {
                    mma16816(d[i][jp * 2 + 0], a[i], &b[jp][0]);
                    mma16816(d[i][jp * 2 + 1], a[i], &b[jp][2]);
                }
        }
    }
    #pragma unroll
    for (int j = 0; j < 8; j++) {
        int c = col0 + wn * 64 + j * 8 + tig * 2;
        #pragma unroll
        for (int i = 0; i < 2; i++) {
            int r = row0 + wm * 32 + i * 16 + q;
            *(__nv_bfloat162*)(g_Tb + (size_t)r * Q_N + c) =
                __nv_bfloat162(__float2bfloat16(d[i][j][0]), __float2bfloat16(d[i][j][1]));
            *(__nv_bfloat162*)(g_Tb + (size_t)(r + 8) * Q_N + c) =
                __nv_bfloat162(__float2bfloat16(d[i][j][2]), __float2bfloat16(d[i][j][3]));
        }
    }
}

// ---------------- kernel 2: filter GEMM + in-kernel candidate collection ----------------
#define ASTRIDE 264
#define G2_BM   128
#define G2_SMEM ((G2_BM + 64) * ASTRIDE * 2)   // 101376 bytes dynamic

__global__ __launch_bounds__(256, 1) void gemm2_tc_kernel() {
    extern __shared__ __align__(16) __nv_bfloat16 sm[];
    __nv_bfloat16* As = sm;                     // [128][264]
    __nv_bfloat16* Bs = sm + G2_BM * ASTRIDE;   // [64][264]
    __shared__ uint32_t s_rowkey[G2_BM];
    __shared__ int      s_cnt[G2_BM];
    __shared__ uint16_t s_cand[G2_BM][CAND_MAX];

    int tid  = threadIdx.x;
    int lane = tid & 31;
    int wid  = tid >> 5;
    int q    = lane >> 2;
    int tig  = lane & 3;
    int wm   = wid & 3;
    int wn   = wid >> 2;
    int row0 = blockIdx.x * G2_BM;

    if (tid < G2_BM) { s_rowkey[tid] = 0xFFFFFFFFu; s_cnt[tid] = 0; }

    // stage resident A
    #pragma unroll
    for (int i = 0; i < 16; i++) {
        int id  = (i << 8) + tid;
        int row = id >> 5;
        int k8  = (id & 31) << 3;
        *(uint4*)(As + row * ASTRIDE + k8) =
            *(const uint4*)(g_Tb + (size_t)(row0 + row) * Q_N + k8);
    }

    // ldmatrix lane addresses
    int g = lane >> 3, idx = lane & 7;
    uint32_t aaddr[2], baddr[2];
    #pragma unroll
    for (int i = 0; i < 2; i++) {
        int r = wm * 32 + i * 16 + ((g & 1) << 3) + idx;
        aaddr[i] = (uint32_t)__cvta_generic_to_shared(As + r * ASTRIDE + (((g >> 1) << 3)));
    }
    #pragma unroll
    for (int jp = 0; jp < 2; jp++) {
        int r = wn * 32 + jp * 16 + ((g >> 1) << 3) + idx;
        baddr[jp] = (uint32_t)__cvta_generic_to_shared(Bs + r * ASTRIDE + ((g & 1) << 3));
    }

    // B staging: each thread owns 8 uint4 slots (c = id>>5, k8 = (id&31)<<3)
    uint4 pf[8];
    #pragma unroll
    for (int i = 0; i < 8; i++) {
        int id = (i << 8) + tid;
        pf[i] = *(const uint4*)(g_CBb + (size_t)(id >> 5) * Q_N + ((id & 31) << 3));
    }
    #pragma unroll
    for (int i = 0; i < 8; i++) {
        int id = (i << 8) + tid;
        *(uint4*)(Bs + (id >> 5) * ASTRIDE + ((id & 31) << 3)) = pf[i];
    }

    int lr[2][2];   // local row indices per (i, half)
    #pragma unroll
    for (int i = 0; i < 2; i++) {
        lr[i][0] = wm * 32 + i * 16 + q;
        lr[i][1] = lr[i][0] + 8;
    }

    for (int nt = 0; nt < C_N / 64; nt++) {
        __syncthreads();   // Bs(nt) visible to all

        // prefetch B(nt+1) into regs during compute
        int ntn = (nt + 1 < C_N / 64) ? nt + 1 : nt;
        #pragma unroll
        for (int i = 0; i < 8; i++) {
            int id = (i << 8) + tid;
            pf[i] = *(const uint4*)(g_CBb + (size_t)(ntn * 64 + (id >> 5)) * Q_N + ((id & 31) << 3));
        }

        float d[2][4][4];
        #pragma unroll
        for (int i = 0; i < 2; i++)
            #pragma unroll
            for (int j = 0; j < 4; j++)
                #pragma unroll
                for (int e = 0; e < 4; e++) d[i][j][e] = 0.f;

        #pragma unroll
        for (int ks = 0; ks < 16; ks++) {
            uint32_t koff = (uint32_t)(ks * 16 * 2);
            uint32_t a[2][4], b[2][4];
            ldsm_x4(a[0], aaddr[0] + koff);
            ldsm_x4(a[1], aaddr[1] + koff);
            ldsm_x4(b[0], baddr[0] + koff);
            ldsm_x4(b[1], baddr[1] + koff);
            #pragma unroll
            for (int i = 0; i < 2; i++) {
                mma16816(d[i][0], a[i], &b[0][0]);
                mma16816(d[i][1], a[i], &b[0][2]);
                mma16816(d[i][2], a[i], &b[1][0]);
                mma16816(d[i][3], a[i], &b[1][2]);
            }
        }

        // epilogue phase 1: per-row local min -> shared atomicMin
        int cbase = nt * 64 + wn * 32;
        float cq[4][2];
        #pragma unroll
        for (int j = 0; j < 4; j++) {
            cq[j][0] = g_cbsq[cbase + j * 8 + tig * 2];
            cq[j][1] = g_cbsq[cbase + j * 8 + tig * 2 + 1];
        }
        float lmin[2][2] = {{3.4e38f, 3.4e38f}, {3.4e38f, 3.4e38f}};
        #pragma unroll
        for (int i = 0; i < 2; i++)
            #pragma unroll
            for (int j = 0; j < 4; j++) {
                float s00 = fmaf(-2.f, d[i][j][0], cq[j][0]);
                float s01 = fmaf(-2.f, d[i][j][1], cq[j][1]);
                float s10 = fmaf(-2.f, d[i][j][2], cq[j][0]);
                float s11 = fmaf(-2.f, d[i][j][3], cq[j][1]);
                lmin[i][0] = fminf(lmin[i][0], fminf(s00, s01));
                lmin[i][1] = fminf(lmin[i][1], fminf(s10, s11));
            }
        #pragma unroll
        for (int i = 0; i < 2; i++) {
            atomicMin(&s_rowkey[lr[i][0]], fkey(lmin[i][0]));
            atomicMin(&s_rowkey[lr[i][1]], fkey(lmin[i][1]));
        }
        __syncthreads();   // all mins for this chunk folded; also Bs consumers done

        // epilogue phase 2: insert candidates vs tightened threshold
        #pragma unroll
        for (int i = 0; i < 2; i++)
            #pragma unroll
            for (int h = 0; h < 2; h++) {
                float thr = funkey(s_rowkey[lr[i][h]]) + RESCUE_DELTA;
                #pragma unroll
                for (int j = 0; j < 4; j++) {
                    float sa = fmaf(-2.f, d[i][j][h * 2 + 0], cq[j][0]);
                    float sb = fmaf(-2.f, d[i][j][h * 2 + 1], cq[j][1]);
                    int c = cbase + j * 8 + tig * 2;
                    if (sa <= thr) {
                        int pos = atomicAdd(&s_cnt[lr[i][h]], 1);
                        if (pos < CAND_MAX) s_cand[lr[i][h]][pos] = (uint16_t)c;
                    }
                    if (sb <= thr) {
                        int pos = atomicAdd(&s_cnt[lr[i][h]], 1);
                        if (pos < CAND_MAX) s_cand[lr[i][h]][pos] = (uint16_t)(c + 1);
                    }
                }
            }

        // store prefetched B(nt+1) (Bs free: consumers synced above)
        #pragma unroll
        for (int i = 0; i < 8; i++) {
            int id = (i << 8) + tid;
            *(uint4*)(Bs + (id >> 5) * ASTRIDE + ((id & 31) << 3)) = pf[i];
        }
    }

    __syncthreads();
    if (tid < G2_BM) {
        g_ncand[row0 + tid] = s_cnt[tid];
        #pragma unroll
        for (int i = 0; i < CAND_MAX / 8; i++)
            *(uint4*)&g_cand[row0 + tid][i * 8] = *(uint4*)&s_cand[tid][i * 8];
    }
}

// ---------------- kernel 3: exact rescue over candidates (U rows, coalesced) ----------------
__global__ __launch_bounds__(256) void rescue_kernel(const float* __restrict__ X,
                                                     float* __restrict__ out) {
    int wid  = threadIdx.x >> 5;
    int lane = threadIdx.x & 31;
    int row  = blockIdx.x * 8 + wid;

    const float* xrow = X + (size_t)row * D_K;
    float x[32];
    #pragma unroll
    for (int t = 0; t < 32; t++) x[t] = xrow[lane + t * 32];

    float bestv = 3.4e38f;
    int   besti = C_N;
    int n = g_ncand[row];

    if (n <= CAND_MAX) {
        for (int i = 0; i < n; i++) {
            int c = g_cand[row][i];
            const float* urow = g_U + (size_t)c * D_K;
            float part = 0.f;
            #pragma unroll 8
            for (int t = 0; t < 32; t++)
                part = fmaf(x[t], urow[lane + t * 32], part);
            #pragma unroll
            for (int off = 16; off > 0; off >>= 1)
                part += __shfl_xor_sync(0xffffffffu, part, off);
            float sc = fmaf(-2.f, part, g_cbsq[c]);
            if (sc < bestv || (sc == bestv && c < besti)) { bestv = sc; besti = c; }
        }
    } else {
        // overflow fallback: exact scan of all C (deterministic, rare)
        for (int c = 0; c < C_N; c++) {
            const float* urow = g_U + (size_t)c * D_K;
            float part = 0.f;
            #pragma unroll 8
            for (int t = 0; t < 32; t++)
                part = fmaf(x[t], urow[lane + t * 32], part);
            #pragma unroll
            for (int off = 16; off > 0; off >>= 1)
                part += __shfl_xor_sync(0xffffffffu, part, off);
            float sc = fmaf(-2.f, part, g_cbsq[c]);
            if (sc < bestv) { bestv = sc; besti = c; }
        }
    }
    if (lane == 0) out[row] = (float)besti;
}

// ---------------- launch ----------------
extern "C" void kernel_launch(void* const* d_in, const int* in_sizes, int n_in,
                              void* d_out, int out_size) {
    (void)out_size;
    const float* X  = 0;
    const float* W  = 0;
    const float* CB = 0;
    for (int i = 0; i < n_in; i++) {
        long long s = (long long)in_sizes[i];
        if      (s == (long long)M_TOTAL * D_K) X  = (const float*)d_in[i];
        else if (s == (long long)Q_N * D_K)     W  = (const float*)d_in[i];
        else if (s == (long long)Q_N * C_N)     CB = (const float*)d_in[i];
    }
    if (!X)  X  = (const float*)d_in[0];
    if (!W  && n_in > 2) W  = (const float*)d_in[2];
    if (!CB && n_in > 3) CB = (const float*)d_in[3];

    float* out = (float*)d_out;

    cudaFuncSetAttribute(gemm2_tc_kernel,
                         cudaFuncAttributeMaxDynamicSharedMemorySize, G2_SMEM);

    cbsq_kernel<<<C_N / 64, 256>>>(CB);
    convCB_kernel<<<(C_N * Q_N) / 256, 256>>>(CB);
    convW_kernel<<<(Q_N * D_K / 4) / 256, 256>>>(W);
    convX_kernel<<<(M_TOTAL * D_K / 4) / 256, 256>>>(X);
    ugemm_kernel<<<dim3(C_N / 64, D_K / 64), 256>>>(CB, W);
    gemm1b_kernel<<<dim3(M_TOTAL / 128, Q_N / 128), 256>>>();
    gemm2_tc_kernel<<<M_TOTAL / G2_BM, 256, G2_SMEM>>>();
    rescue_kernel<<<M_TOTAL / 8, 256>>>(X, out);
}

// round 10
// speedup vs baseline: 3.9383x; 1.1461x over previous
#include <cuda_runtime.h>
#include <cuda_bf16.h>
#include <cstdint>

// Problem constants (fixed shapes from reference)
#define M_TOTAL 16384   // B*L
#define D_K     1024    // D
#define Q_N     256     // Q
#define C_N     4096    // C

#define CAND_MAX 32
#define RESCUE_DELTA 6.0f

// Scratch (device globals: allowed; no allocation APIs)
__device__ float          g_cbsq[C_N];            // ||codebook[:,c]||^2 (fp32 exact)
__device__ __nv_bfloat16  g_Wb[Q_N * D_K];        // bf16 W (512KB)
__device__ __nv_bfloat16  g_Tb[M_TOTAL * Q_N];    // bf16 targets (8MB)
__device__ __nv_bfloat16  g_CBb[C_N * Q_N];       // bf16 codebook, [c][k] (2MB)
__device__ float          g_U[(size_t)C_N * D_K]; // U[c][d] = sum_q CB[q][c] W[q][d] (16MB)
__device__ int            g_ncand[M_TOTAL];
__device__ uint16_t       g_cand[M_TOTAL][CAND_MAX];

// ---------------- packed fp32x2 helpers (FFMA2, validated R5/R7) ----------------
__device__ __forceinline__ void fma2(unsigned long long& d,
                                     unsigned long long a,
                                     unsigned long long b) {
    asm("fma.rn.f32x2 %0, %1, %2, %0;" : "+l"(d) : "l"(a), "l"(b));
}
__device__ __forceinline__ unsigned long long pack2(float x) {
    unsigned long long r;
    unsigned u = __float_as_uint(x);
    asm("mov.b64 %0, {%1, %2};" : "=l"(r) : "r"(u), "r"(u));
    return r;
}
__device__ __forceinline__ float lo32(unsigned long long v) {
    return __uint_as_float((unsigned)(v & 0xffffffffull));
}
__device__ __forceinline__ float hi32(unsigned long long v) {
    return __uint_as_float((unsigned)(v >> 32));
}

// ---------------- warp MMA + ldmatrix + cp.async ----------------
__device__ __forceinline__ void mma16816(float* d, const uint32_t* a, const uint32_t* b) {
    asm volatile(
        "mma.sync.aligned.m16n8k16.row.col.f32.bf16.bf16.f32 "
        "{%0,%1,%2,%3}, {%4,%5,%6,%7}, {%8,%9}, {%0,%1,%2,%3};"
        : "+f"(d[0]), "+f"(d[1]), "+f"(d[2]), "+f"(d[3])
        : "r"(a[0]), "r"(a[1]), "r"(a[2]), "r"(a[3]), "r"(b[0]), "r"(b[1]));
}
__device__ __forceinline__ void ldsm_x4(uint32_t* r, uint32_t addr) {
    asm volatile("ldmatrix.sync.aligned.m8n8.x4.shared.b16 {%0,%1,%2,%3}, [%4];"
                 : "=r"(r[0]), "=r"(r[1]), "=r"(r[2]), "=r"(r[3]) : "r"(addr));
}
__device__ __forceinline__ void cp_async16(uint32_t dst, const void* src) {
    asm volatile("cp.async.cg.shared.global [%0], [%1], 16;" :: "r"(dst), "l"(src));
}
#define CP_COMMIT() asm volatile("cp.async.commit_group;" ::: "memory")
#define CP_WAIT1()  asm volatile("cp.async.wait_group 1;" ::: "memory")

// order-preserving float<->uint key (for atomicMin on scores of any sign)
__device__ __forceinline__ uint32_t fkey(float f) {
    uint32_t b = __float_as_uint(f);
    return (b & 0x80000000u) ? ~b : (b | 0x80000000u);
}
__device__ __forceinline__ float funkey(uint32_t k) {
    uint32_t b = (k & 0x80000000u) ? (k & 0x7FFFFFFFu) : ~k;
    return __uint_as_float(b);
}

// ---------------- kernel 0: cb_sq ----------------
__global__ __launch_bounds__(256) void cbsq_kernel(const float* __restrict__ CB) {
    __shared__ float red[4][64];
    int t = threadIdx.x;
    int c = blockIdx.x * 64 + (t & 63);
    int part = t >> 6;
    float s = 0.f;
    #pragma unroll 8
    for (int k = part * 64; k < part * 64 + 64; k++) {
        float v = CB[(size_t)k * C_N + c];
        s = fmaf(v, v, s);
    }
    red[part][t & 63] = s;
    __syncthreads();
    if (t < 64)
        g_cbsq[blockIdx.x * 64 + t] = red[0][t] + red[1][t] + red[2][t] + red[3][t];
}

// ---------------- conversion kernels ----------------
__global__ __launch_bounds__(256) void convW_kernel(const float* __restrict__ W) {
    int idx = blockIdx.x * 256 + threadIdx.x;
    float4 v = ((const float4*)W)[idx];
    __nv_bfloat162* o = (__nv_bfloat162*)g_Wb + idx * 2;
    o[0] = __nv_bfloat162(__float2bfloat16(v.x), __float2bfloat16(v.y));
    o[1] = __nv_bfloat162(__float2bfloat16(v.z), __float2bfloat16(v.w));
}
__global__ __launch_bounds__(256) void convCB_kernel(const float* __restrict__ CB) {
    int o = blockIdx.x * 256 + threadIdx.x;
    int k = o & 255;
    int c = o >> 8;
    g_CBb[o] = __float2bfloat16(CB[(size_t)k * C_N + c]);
}

// ---------------- kernel U: U = CB^T @ W  (fp32 FFMA2, validated R8) ----------------
__global__ __launch_bounds__(256) void ugemm_kernel(const float* __restrict__ CB,
                                                    const float* __restrict__ W) {
    __shared__ __align__(16) float As[32][64];
    __shared__ __align__(16) float Bs[32][64];
    int tid = threadIdx.x;
    int tr = tid >> 4;
    int tc = tid & 15;
    int row0 = blockIdx.x << 6;   // c
    int col0 = blockIdx.y << 6;   // d

    unsigned long long acc[2][4];
    #pragma unroll
    for (int p = 0; p < 2; p++)
        #pragma unroll
        for (int j = 0; j < 4; j++) acc[p][j] = 0ull;

    for (int kc = 0; kc < Q_N; kc += 32) {
        __syncthreads();
        #pragma unroll
        for (int i = 0; i < 2; i++) {
            int f4 = (i << 8) + tid;
            int q  = f4 >> 4;
            int e4 = (f4 & 15) << 2;
            *(float4*)&As[q][e4] = *(const float4*)(CB + (size_t)(kc + q) * C_N + row0 + e4);
            *(float4*)&Bs[q][e4] = *(const float4*)(W  + (size_t)(kc + q) * D_K + col0 + e4);
        }
        __syncthreads();
        #pragma unroll
        for (int k = 0; k < 32; k++) {
            ulonglong2 a = *(const ulonglong2*)&As[k][tr << 2];
            float4 b = *(const float4*)&Bs[k][tc << 2];
            unsigned long long bb0 = pack2(b.x), bb1 = pack2(b.y);
            unsigned long long bb2 = pack2(b.z), bb3 = pack2(b.w);
            fma2(acc[0][0], a.x, bb0); fma2(acc[0][1], a.x, bb1);
            fma2(acc[0][2], a.x, bb2); fma2(acc[0][3], a.x, bb3);
            fma2(acc[1][0], a.y, bb0); fma2(acc[1][1], a.y, bb1);
            fma2(acc[1][2], a.y, bb2); fma2(acc[1][3], a.y, bb3);
        }
    }
    #pragma unroll
    for (int p = 0; p < 2; p++) {
        int c = row0 + (tr << 2) + (p << 1);
        #pragma unroll
        for (int j = 0; j < 4; j++) {
            int d = col0 + (tc << 2) + j;
            g_U[(size_t)c       * D_K + d] = lo32(acc[p][j]);
            g_U[(size_t)(c + 1) * D_K + d] = hi32(acc[p][j]);
        }
    }
}

// ---------------- kernel 1: T~ = bf16(X) @ bf16(W)^T  (fused X conversion) ----------------
#define T_STRIDE 72
__global__ __launch_bounds__(256, 2) void gemm1b_kernel(const float* __restrict__ X) {
    __shared__ __align__(16) __nv_bfloat16 As[128][T_STRIDE];
    __shared__ __align__(16) __nv_bfloat16 Bs[128][T_STRIDE];

    int tid  = threadIdx.x;
    int wid  = tid >> 5;
    int lane = tid & 31;
    int q    = lane >> 2;
    int tig  = lane & 3;
    int wm   = wid & 3;
    int wn   = wid >> 2;
    int row0 = blockIdx.x << 7;
    int col0 = blockIdx.y << 7;

    // per-lane ldmatrix base addresses (mapping validated R9)
    int g   = lane >> 3, idx = lane & 7;
    uint32_t aaddr[2], baddr[4];
    #pragma unroll
    for (int i = 0; i < 2; i++) {
        int r = wm * 32 + i * 16 + ((g & 1) << 3) + idx;
        aaddr[i] = (uint32_t)__cvta_generic_to_shared(&As[r][(g >> 1) << 3]);
    }
    #pragma unroll
    for (int jp = 0; jp < 4; jp++) {
        int r = wn * 64 + jp * 16 + ((g >> 1) << 3) + idx;
        baddr[jp] = (uint32_t)__cvta_generic_to_shared(&Bs[r][(g & 1) << 3]);
    }

    float d[2][8][4];
    #pragma unroll
    for (int i = 0; i < 2; i++)
        #pragma unroll
        for (int j = 0; j < 8; j++)
            #pragma unroll
            for (int e = 0; e < 4; e++) d[i][j][e] = 0.f;

    for (int kc = 0; kc < D_K; kc += 64) {
        __syncthreads();
        // A: read fp32 X, convert to bf16 in-flight
        #pragma unroll
        for (int i = 0; i < 8; i++) {
            int fi  = (i << 8) + tid;          // 0..2047 float4s
            int row = fi >> 4;                 // 0..127
            int c4  = (fi & 15) << 2;          // 0..60
            float4 v = *(const float4*)(X + (size_t)(row0 + row) * D_K + kc + c4);
            *(__nv_bfloat162*)&As[row][c4] =
                __nv_bfloat162(__float2bfloat16(v.x), __float2bfloat16(v.y));
            *(__nv_bfloat162*)&As[row][c4 + 2] =
                __nv_bfloat162(__float2bfloat16(v.z), __float2bfloat16(v.w));
        }
        // B: bf16 W
        #pragma unroll
        for (int i = 0; i < 4; i++) {
            int id  = (i << 8) + tid;          // 0..1023 uint4s
            int row = id >> 3;
            int k8  = (id & 7) << 3;
            *(uint4*)&Bs[row][k8] = *(const uint4*)(g_Wb + (size_t)(col0 + row) * D_K + kc + k8);
        }
        __syncthreads();
        #pragma unroll
        for (int ks = 0; ks < 4; ks++) {
            uint32_t koff = (uint32_t)(ks * 16 * 2);
            uint32_t a[2][4], b[4][4];
            ldsm_x4(a[0], aaddr[0] + koff);
            ldsm_x4(a[1], aaddr[1] + koff);
            #pragma unroll
            for (int jp = 0; jp < 4; jp++) ldsm_x4(b[jp], baddr[jp] + koff);
            #pragma unroll
            for (int i = 0; i < 2; i++)
                #pragma unroll
                for (int jp = 0; jp < 4; jp++) {
                    mma16816(d[i][jp * 2 + 0], a[i], &b[jp][0]);
                    mma16816(d[i][jp * 2 + 1], a[i], &b[jp][2]);
                }
        }
    }
    #pragma unroll
    for (int j = 0; j < 8; j++) {
        int c = col0 + wn * 64 + j * 8 + tig * 2;
        #pragma unroll
        for (int i = 0; i < 2; i++) {
            int r = row0 + wm * 32 + i * 16 + q;
            *(__nv_bfloat162*)(g_Tb + (size_t)r * Q_N + c) =
                __nv_bfloat162(__float2bfloat16(d[i][j][0]), __float2bfloat16(d[i][j][1]));
            *(__nv_bfloat162*)(g_Tb + (size_t)(r + 8) * Q_N + c) =
                __nv_bfloat162(__float2bfloat16(d[i][j][2]), __float2bfloat16(d[i][j][3]));
        }
    }
}

// ---------------- kernel 2: filter GEMM, N=128/iter, cp.async double-buffered B ----------------
#define ASTRIDE 264
#define G2_BM   128
#define G2_BN   128
#define B_BUF_ELEMS (G2_BN * ASTRIDE)
#define G2_SMEM ((G2_BM + 2 * G2_BN) * ASTRIDE * 2)   // 202752 bytes dynamic
#define NT_CNT  (C_N / G2_BN)                          // 32

__global__ __launch_bounds__(256, 1) void gemm2_tc_kernel() {
    extern __shared__ __align__(16) __nv_bfloat16 sm[];
    __nv_bfloat16* As  = sm;                       // [128][264]
    __nv_bfloat16* Bs0 = sm + G2_BM * ASTRIDE;     // 2 x [128][264]
    __shared__ uint32_t s_rowkey[G2_BM];
    __shared__ int      s_cnt[G2_BM];
    __shared__ uint16_t s_cand[G2_BM][CAND_MAX];

    int tid  = threadIdx.x;
    int lane = tid & 31;
    int wid  = tid >> 5;
    int q    = lane >> 2;
    int tig  = lane & 3;
    int wm   = wid & 3;        // rows wm*32..+31
    int wn   = wid >> 2;       // cols wn*64..+63 within 128-chunk
    int row0 = blockIdx.x * G2_BM;

    if (tid < G2_BM) { s_rowkey[tid] = 0xFFFFFFFFu; s_cnt[tid] = 0; }

    // stage resident A
    #pragma unroll
    for (int i = 0; i < 16; i++) {
        int id  = (i << 8) + tid;
        int row = id >> 5;
        int k8  = (id & 31) << 3;
        *(uint4*)(As + row * ASTRIDE + k8) =
            *(const uint4*)(g_Tb + (size_t)(row0 + row) * Q_N + k8);
    }

    uint32_t bsb[2];
    bsb[0] = (uint32_t)__cvta_generic_to_shared(Bs0);
    bsb[1] = (uint32_t)__cvta_generic_to_shared(Bs0 + B_BUF_ELEMS);

    // ldmatrix lane addresses
    int g = lane >> 3, idx = lane & 7;
    uint32_t aaddr[2], baddr[2][4];
    #pragma unroll
    for (int i = 0; i < 2; i++) {
        int r = wm * 32 + i * 16 + ((g & 1) << 3) + idx;
        aaddr[i] = (uint32_t)__cvta_generic_to_shared(As + r * ASTRIDE + ((g >> 1) << 3));
    }
    #pragma unroll
    for (int p = 0; p < 2; p++)
        #pragma unroll
        for (int jp = 0; jp < 4; jp++) {
            int r = wn * 64 + jp * 16 + ((g >> 1) << 3) + idx;
            baddr[p][jp] = bsb[p] + (uint32_t)((r * ASTRIDE + ((g & 1) << 3)) * 2);
        }

    // cp.async B staging: 128 rows x 256 k bf16 per chunk -> 16 x 16B per thread
    #define ISSUE_B(nt_, p_)                                                        \
        do {                                                                        \
            const __nv_bfloat16* src = g_CBb + (size_t)((nt_) * G2_BN) * Q_N;       \
            _Pragma("unroll")                                                       \
            for (int i_ = 0; i_ < 16; i_++) {                                       \
                int id_  = (i_ << 8) + tid;                                         \
                int row_ = id_ >> 5;                                                \
                int k8_  = (id_ & 31) << 3;                                         \
                cp_async16(bsb[p_] + (uint32_t)((row_ * ASTRIDE + k8_) * 2),        \
                           src + (size_t)row_ * Q_N + k8_);                         \
            }                                                                       \
        } while (0)

    ISSUE_B(0, 0); CP_COMMIT();
    ISSUE_B(1, 1); CP_COMMIT();

    int lr[2][2];
    #pragma unroll
    for (int i = 0; i < 2; i++) {
        lr[i][0] = wm * 32 + i * 16 + q;
        lr[i][1] = lr[i][0] + 8;
    }

    for (int nt = 0; nt < NT_CNT; nt++) {
        int p = nt & 1;
        CP_WAIT1();          // own slices of buffer p complete
        __syncthreads();     // everyone's slices complete (also A/init on nt==0)

        float d[2][8][4];
        #pragma unroll
        for (int i = 0; i < 2; i++)
            #pragma unroll
            for (int j = 0; j < 8; j++)
                #pragma unroll
                for (int e = 0; e < 4; e++) d[i][j][e] = 0.f;

        #pragma unroll
        for (int ks = 0; ks < 16; ks++) {
            uint32_t koff = (uint32_t)(ks * 16 * 2);
            uint32_t a[2][4], b[4][4];
            ldsm_x4(a[0], aaddr[0] + koff);
            ldsm_x4(a[1], aaddr[1] + koff);
            #pragma unroll
            for (int jp = 0; jp < 4; jp++) ldsm_x4(b[jp], baddr[p][jp] + koff);
            #pragma unroll
            for (int i = 0; i < 2; i++)
                #pragma unroll
                for (int jp = 0; jp < 4; jp++) {
                    mma16816(d[i][jp * 2 + 0], a[i], &b[jp][0]);
                    mma16816(d[i][jp * 2 + 1], a[i], &b[jp][2]);
                }
        }

        // epilogue phase 1: per-row local min -> shared atomicMin
        int cbase = nt * G2_BN + wn * 64;
        float cq[8][2];
        #pragma unroll
        for (int j = 0; j < 8; j++) {
            cq[j][0] = g_cbsq[cbase + j * 8 + tig * 2];
            cq[j][1] = g_cbsq[cbase + j * 8 + tig * 2 + 1];
        }
        float lmin[2][2] = {{3.4e38f, 3.4e38f}, {3.4e38f, 3.4e38f}};
        #pragma unroll
        for (int i = 0; i < 2; i++)
            #pragma unroll
            for (int j = 0; j < 8; j++) {
                float s00 = fmaf(-2.f, d[i][j][0], cq[j][0]);
                float s01 = fmaf(-2.f, d[i][j][1], cq[j][1]);
                float s10 = fmaf(-2.f, d[i][j][2], cq[j][0]);
                float s11 = fmaf(-2.f, d[i][j][3], cq[j][1]);
                lmin[i][0] = fminf(lmin[i][0], fminf(s00, s01));
                lmin[i][1] = fminf(lmin[i][1], fminf(s10, s11));
            }
        #pragma unroll
        for (int i = 0; i < 2; i++) {
            atomicMin(&s_rowkey[lr[i][0]], fkey(lmin[i][0]));
            atomicMin(&s_rowkey[lr[i][1]], fkey(lmin[i][1]));
        }
        __syncthreads();     // mins folded; all warps done reading buffer p

        // epilogue phase 2: insert candidates vs tightened threshold (regs only)
        #pragma unroll
        for (int i = 0; i < 2; i++)
            #pragma unroll
            for (int h = 0; h < 2; h++) {
                float thr = funkey(s_rowkey[lr[i][h]]) + RESCUE_DELTA;
                #pragma unroll
                for (int j = 0; j < 8; j++) {
                    float sa = fmaf(-2.f, d[i][j][h * 2 + 0], cq[j][0]);
                    float sb = fmaf(-2.f, d[i][j][h * 2 + 1], cq[j][1]);
                    int c = cbase + j * 8 + tig * 2;
                    if (sa <= thr) {
                        int pos = atomicAdd(&s_cnt[lr[i][h]], 1);
                        if (pos < CAND_MAX) s_cand[lr[i][h]][pos] = (uint16_t)c;
                    }
                    if (sb <= thr) {
                        int pos = atomicAdd(&s_cnt[lr[i][h]], 1);
                        if (pos < CAND_MAX) s_cand[lr[i][h]][pos] = (uint16_t)(c + 1);
                    }
                }
            }

        // issue B(nt+2) into buffer p (safe: post-sync, all consumers done)
        if (nt + 2 < NT_CNT) ISSUE_B(nt + 2, p);
        CP_COMMIT();
    }

    __syncthreads();
    if (tid < G2_BM) {
        g_ncand[row0 + tid] = s_cnt[tid];
        #pragma unroll
        for (int i = 0; i < CAND_MAX / 8; i++)
            *(uint4*)&g_cand[row0 + tid][i * 8] = *(uint4*)&s_cand[tid][i * 8];
    }
}

// ---------------- kernel 3: exact rescue over candidates (U rows, coalesced) ----------------
__global__ __launch_bounds__(256) void rescue_kernel(const float* __restrict__ X,
                                                     float* __restrict__ out) {
    int wid  = threadIdx.x >> 5;
    int lane = threadIdx.x & 31;
    int row  = blockIdx.x * 8 + wid;

    const float* xrow = X + (size_t)row * D_K;
    float x[32];
    #pragma unroll
    for (int t = 0; t < 32; t++) x[t] = xrow[lane + t * 32];

    float bestv = 3.4e38f;
    int   besti = C_N;
    int n = g_ncand[row];

    if (n <= CAND_MAX) {
        for (int i = 0; i < n; i++) {
            int c = g_cand[row][i];
            const float* urow = g_U + (size_t)c * D_K;
            float part = 0.f;
            #pragma unroll 8
            for (int t = 0; t < 32; t++)
                part = fmaf(x[t], urow[lane + t * 32], part);
            #pragma unroll
            for (int off = 16; off > 0; off >>= 1)
                part += __shfl_xor_sync(0xffffffffu, part, off);
            float sc = fmaf(-2.f, part, g_cbsq[c]);
            if (sc < bestv || (sc == bestv && c < besti)) { bestv = sc; besti = c; }
        }
    } else {
        // overflow fallback: exact scan of all C (deterministic, rare)
        for (int c = 0; c < C_N; c++) {
            const float* urow = g_U + (size_t)c * D_K;
            float part = 0.f;
            #pragma unroll 8
            for (int t = 0; t < 32; t++)
                part = fmaf(x[t], urow[lane + t * 32], part);
            #pragma unroll
            for (int off = 16; off > 0; off >>= 1)
                part += __shfl_xor_sync(0xffffffffu, part, off);
            float sc = fmaf(-2.f, part, g_cbsq[c]);
            if (sc < bestv) { bestv = sc; besti = c; }
        }
    }
    if (lane == 0) out[row] = (float)besti;
}

// ---------------- launch ----------------
extern "C" void kernel_launch(void* const* d_in, const int* in_sizes, int n_in,
                              void* d_out, int out_size) {
    (void)out_size;
    const float* X  = 0;
    const float* W  = 0;
    const float* CB = 0;
    for (int i = 0; i < n_in; i++) {
        long long s = (long long)in_sizes[i];
        if      (s == (long long)M_TOTAL * D_K) X  = (const float*)d_in[i];
        else if (s == (long long)Q_N * D_K)     W  = (const float*)d_in[i];
        else if (s == (long long)Q_N * C_N)     CB = (const float*)d_in[i];
    }
    if (!X)  X  = (const float*)d_in[0];
    if (!W  && n_in > 2) W  = (const float*)d_in[2];
    if (!CB && n_in > 3) CB = (const float*)d_in[3];

    float* out = (float*)d_out;

    cudaFuncSetAttribute(gemm2_tc_kernel,
                         cudaFuncAttributeMaxDynamicSharedMemorySize, G2_SMEM);

    cbsq_kernel<<<C_N / 64, 256>>>(CB);
    convCB_kernel<<<(C_N * Q_N) / 256, 256>>>(CB);
    convW_kernel<<<(Q_N * D_K / 4) / 256, 256>>>(W);
    ugemm_kernel<<<dim3(C_N / 64, D_K / 64), 256>>>(CB, W);
    gemm1b_kernel<<<dim3(M_TOTAL / 128, Q_N / 128), 256>>>(X);
    gemm2_tc_kernel<<<M_TOTAL / G2_BM, 256, G2_SMEM>>>();
    rescue_kernel<<<M_TOTAL / 8, 256>>>(X, out);
}

// round 11
// speedup vs baseline: 4.0212x; 1.0211x over previous
#include <cuda_runtime.h>
#include <cuda_bf16.h>
#include <cstdint>

// Problem constants (fixed shapes from reference)
#define M_TOTAL 16384   // B*L
#define D_K     1024    // D
#define Q_N     256     // Q
#define C_N     4096    // C

#define CAND_MAX 32
#define RESCUE_DELTA 6.0f

// Scratch (device globals: allowed; no allocation APIs)
__device__ float          g_cbsq[C_N];            // ||codebook[:,c]||^2 (fp32 exact)
__device__ __nv_bfloat16  g_Wb[Q_N * D_K];        // bf16 W (512KB)
__device__ __nv_bfloat16  g_Tb[M_TOTAL * Q_N];    // bf16 targets (8MB)
__device__ __nv_bfloat16  g_CBb[C_N * Q_N];       // bf16 codebook, [c][k] (2MB)
__device__ float          g_U[(size_t)C_N * D_K]; // U[c][d] = sum_q CB[q][c] W[q][d] (16MB)
__device__ int            g_ncand[M_TOTAL];
__device__ uint16_t       g_cand[M_TOTAL][CAND_MAX];

// ---------------- packed fp32x2 helpers (FFMA2, validated R5/R7) ----------------
__device__ __forceinline__ void fma2(unsigned long long& d,
                                     unsigned long long a,
                                     unsigned long long b) {
    asm("fma.rn.f32x2 %0, %1, %2, %0;" : "+l"(d) : "l"(a), "l"(b));
}
__device__ __forceinline__ unsigned long long pack2(float x) {
    unsigned long long r;
    unsigned u = __float_as_uint(x);
    asm("mov.b64 %0, {%1, %2};" : "=l"(r) : "r"(u), "r"(u));
    return r;
}
__device__ __forceinline__ float lo32(unsigned long long v) {
    return __uint_as_float((unsigned)(v & 0xffffffffull));
}
__device__ __forceinline__ float hi32(unsigned long long v) {
    return __uint_as_float((unsigned)(v >> 32));
}

// ---------------- warp MMA + ldmatrix + cp.async ----------------
__device__ __forceinline__ void mma16816(float* d, const uint32_t* a, const uint32_t* b) {
    asm volatile(
        "mma.sync.aligned.m16n8k16.row.col.f32.bf16.bf16.f32 "
        "{%0,%1,%2,%3}, {%4,%5,%6,%7}, {%8,%9}, {%0,%1,%2,%3};"
        : "+f"(d[0]), "+f"(d[1]), "+f"(d[2]), "+f"(d[3])
        : "r"(a[0]), "r"(a[1]), "r"(a[2]), "r"(a[3]), "r"(b[0]), "r"(b[1]));
}
__device__ __forceinline__ void ldsm_x4(uint32_t* r, uint32_t addr) {
    asm volatile("ldmatrix.sync.aligned.m8n8.x4.shared.b16 {%0,%1,%2,%3}, [%4];"
                 : "=r"(r[0]), "=r"(r[1]), "=r"(r[2]), "=r"(r[3]) : "r"(addr));
}
__device__ __forceinline__ void cp_async16(uint32_t dst, const void* src) {
    asm volatile("cp.async.cg.shared.global [%0], [%1], 16;" :: "r"(dst), "l"(src));
}
#define CP_COMMIT() asm volatile("cp.async.commit_group;" ::: "memory")
#define CP_WAIT1()  asm volatile("cp.async.wait_group 1;" ::: "memory")

// order-preserving float<->uint key (for atomicMin on scores of any sign)
__device__ __forceinline__ uint32_t fkey(float f) {
    uint32_t b = __float_as_uint(f);
    return (b & 0x80000000u) ? ~b : (b | 0x80000000u);
}
__device__ __forceinline__ float funkey(uint32_t k) {
    uint32_t b = (k & 0x80000000u) ? (k & 0x7FFFFFFFu) : ~k;
    return __uint_as_float(b);
}

// ---------------- prep kernel: cbsq + convCB + convW fused ----------------
// blocks [0,64): cbsq  | [64, 64+4096): convCB | [4160, 4416): convW
__global__ __launch_bounds__(256) void prep_kernel(const float* __restrict__ CB,
                                                   const float* __restrict__ W) {
    __shared__ float red[4][64];
    int b = blockIdx.x;
    int t = threadIdx.x;
    if (b < 64) {
        int c = b * 64 + (t & 63);
        int part = t >> 6;
        float s = 0.f;
        #pragma unroll 8
        for (int k = part * 64; k < part * 64 + 64; k++) {
            float v = CB[(size_t)k * C_N + c];
            s = fmaf(v, v, s);
        }
        red[part][t & 63] = s;
        __syncthreads();
        if (t < 64)
            g_cbsq[b * 64 + t] = red[0][t] + red[1][t] + red[2][t] + red[3][t];
    } else if (b < 64 + 4096) {
        int o = (b - 64) * 256 + t;         // over 1M elems
        int k = o & 255;
        int c = o >> 8;
        g_CBb[o] = __float2bfloat16(CB[(size_t)k * C_N + c]);
    } else {
        int idx = (b - 4160) * 256 + t;     // over 64K float4s
        float4 v = ((const float4*)W)[idx];
        __nv_bfloat162* o = (__nv_bfloat162*)g_Wb + idx * 2;
        o[0] = __nv_bfloat162(__float2bfloat16(v.x), __float2bfloat16(v.y));
        o[1] = __nv_bfloat162(__float2bfloat16(v.z), __float2bfloat16(v.w));
    }
}

// ---------------- kernel U: U = CB^T @ W  (fp32 FFMA2, 8x4 microtile) ----------------
// M=4096 (c), N=1024 (d), K=256 (q).  BM=128, BN=64, BK=32.  256 threads,
// 8 rows x 4 cols per thread; acc packed f32x2 along row pairs.
__global__ __launch_bounds__(256) void ugemm_kernel(const float* __restrict__ CB,
                                                    const float* __restrict__ W) {
    __shared__ __align__(16) float As[32][128];  // [q][c] 16KB
    __shared__ __align__(16) float Bs[32][64];   // [q][d]  8KB
    int tid = threadIdx.x;
    int tr = tid >> 4;            // 0..15 -> rows tr*8..tr*8+7
    int tc = tid & 15;            // 0..15 -> cols tc*4..tc*4+3
    int row0 = blockIdx.x << 7;   // c
    int col0 = blockIdx.y << 6;   // d

    unsigned long long acc[4][4];
    #pragma unroll
    for (int p = 0; p < 4; p++)
        #pragma unroll
        for (int j = 0; j < 4; j++) acc[p][j] = 0ull;

    for (int kc = 0; kc < Q_N; kc += 32) {
        __syncthreads();
        // stage A: 32 q x 128 c = 1024 float4 (4/thread); B: 512 float4 (2/thread)
        #pragma unroll
        for (int i = 0; i < 4; i++) {
            int f4 = (i << 8) + tid;
            int q  = f4 >> 5;                 // 0..31
            int e4 = (f4 & 31) << 2;          // 0..124
            *(float4*)&As[q][e4] = *(const float4*)(CB + (size_t)(kc + q) * C_N + row0 + e4);
        }
        #pragma unroll
        for (int i = 0; i < 2; i++) {
            int f4 = (i << 8) + tid;
            int q  = f4 >> 4;                 // 0..31
            int e4 = (f4 & 15) << 2;          // 0..60
            *(float4*)&Bs[q][e4] = *(const float4*)(W + (size_t)(kc + q) * D_K + col0 + e4);
        }
        __syncthreads();
        #pragma unroll
        for (int k = 0; k < 32; k++) {
            ulonglong2 a01 = *(const ulonglong2*)&As[k][tr << 3];       // rows (0,1),(2,3)
            ulonglong2 a23 = *(const ulonglong2*)&As[k][(tr << 3) + 4]; // rows (4,5),(6,7)
            float4 b = *(const float4*)&Bs[k][tc << 2];
            unsigned long long bb0 = pack2(b.x), bb1 = pack2(b.y);
            unsigned long long bb2 = pack2(b.z), bb3 = pack2(b.w);
            fma2(acc[0][0], a01.x, bb0); fma2(acc[0][1], a01.x, bb1);
            fma2(acc[0][2], a01.x, bb2); fma2(acc[0][3], a01.x, bb3);
            fma2(acc[1][0], a01.y, bb0); fma2(acc[1][1], a01.y, bb1);
            fma2(acc[1][2], a01.y, bb2); fma2(acc[1][3], a01.y, bb3);
            fma2(acc[2][0], a23.x, bb0); fma2(acc[2][1], a23.x, bb1);
            fma2(acc[2][2], a23.x, bb2); fma2(acc[2][3], a23.x, bb3);
            fma2(acc[3][0], a23.y, bb0); fma2(acc[3][1], a23.y, bb1);
            fma2(acc[3][2], a23.y, bb2); fma2(acc[3][3], a23.y, bb3);
        }
    }
    #pragma unroll
    for (int p = 0; p < 4; p++) {
        int c = row0 + (tr << 3) + (p << 1);
        #pragma unroll
        for (int j = 0; j < 4; j++) {
            int d = col0 + (tc << 2) + j;
            g_U[(size_t)c       * D_K + d] = lo32(acc[p][j]);
            g_U[(size_t)(c + 1) * D_K + d] = hi32(acc[p][j]);
        }
    }
}

// ---------------- kernel 1: T~ = bf16(X) @ bf16(W)^T  (fused X conversion, validated R10) ----------------
#define T_STRIDE 72
__global__ __launch_bounds__(256, 2) void gemm1b_kernel(const float* __restrict__ X) {
    __shared__ __align__(16) __nv_bfloat16 As[128][T_STRIDE];
    __shared__ __align__(16) __nv_bfloat16 Bs[128][T_STRIDE];

    int tid  = threadIdx.x;
    int wid  = tid >> 5;
    int lane = tid & 31;
    int q    = lane >> 2;
    int tig  = lane & 3;
    int wm   = wid & 3;
    int wn   = wid >> 2;
    int row0 = blockIdx.x << 7;
    int col0 = blockIdx.y << 7;

    int g   = lane >> 3, idx = lane & 7;
    uint32_t aaddr[2], baddr[4];
    #pragma unroll
    for (int i = 0; i < 2; i++) {
        int r = wm * 32 + i * 16 + ((g & 1) << 3) + idx;
        aaddr[i] = (uint32_t)__cvta_generic_to_shared(&As[r][(g >> 1) << 3]);
    }
    #pragma unroll
    for (int jp = 0; jp < 4; jp++) {
        int r = wn * 64 + jp * 16 + ((g >> 1) << 3) + idx;
        baddr[jp] = (uint32_t)__cvta_generic_to_shared(&Bs[r][(g & 1) << 3]);
    }

    float d[2][8][4];
    #pragma unroll
    for (int i = 0; i < 2; i++)
        #pragma unroll
        for (int j = 0; j < 8; j++)
            #pragma unroll
            for (int e = 0; e < 4; e++) d[i][j][e] = 0.f;

    for (int kc = 0; kc < D_K; kc += 64) {
        __syncthreads();
        #pragma unroll
        for (int i = 0; i < 8; i++) {
            int fi  = (i << 8) + tid;
            int row = fi >> 4;
            int c4  = (fi & 15) << 2;
            float4 v = *(const float4*)(X + (size_t)(row0 + row) * D_K + kc + c4);
            *(__nv_bfloat162*)&As[row][c4] =
                __nv_bfloat162(__float2bfloat16(v.x), __float2bfloat16(v.y));
            *(__nv_bfloat162*)&As[row][c4 + 2] =
                __nv_bfloat162(__float2bfloat16(v.z), __float2bfloat16(v.w));
        }
        #pragma unroll
        for (int i = 0; i < 4; i++) {
            int id  = (i << 8) + tid;
            int row = id >> 3;
            int k8  = (id & 7) << 3;
            *(uint4*)&Bs[row][k8] = *(const uint4*)(g_Wb + (size_t)(col0 + row) * D_K + kc + k8);
        }
        __syncthreads();
        #pragma unroll
        for (int ks = 0; ks < 4; ks++) {
            uint32_t koff = (uint32_t)(ks * 16 * 2);
            uint32_t a[2][4], b[4][4];
            ldsm_x4(a[0], aaddr[0] + koff);
            ldsm_x4(a[1], aaddr[1] + koff);
            #pragma unroll
            for (int jp = 0; jp < 4; jp++) ldsm_x4(b[jp], baddr[jp] + koff);
            #pragma unroll
            for (int i = 0; i < 2; i++)
                #pragma unroll
                for (int jp = 0; jp < 4; jp++) {
                    mma16816(d[i][jp * 2 + 0], a[i], &b[jp][0]);
                    mma16816(d[i][jp * 2 + 1], a[i], &b[jp][2]);
                }
        }
    }
    #pragma unroll
    for (int j = 0; j < 8; j++) {
        int c = col0 + wn * 64 + j * 8 + tig * 2;
        #pragma unroll
        for (int i = 0; i < 2; i++) {
            int r = row0 + wm * 32 + i * 16 + q;
            *(__nv_bfloat162*)(g_Tb + (size_t)r * Q_N + c) =
                __nv_bfloat162(__float2bfloat16(d[i][j][0]), __float2bfloat16(d[i][j][1]));
            *(__nv_bfloat162*)(g_Tb + (size_t)(r + 8) * Q_N + c) =
                __nv_bfloat162(__float2bfloat16(d[i][j][2]), __float2bfloat16(d[i][j][3]));
        }
    }
}

// ---------------- kernel 2: filter GEMM, N=128/iter, cp.async double-buffered B ----------------
#define ASTRIDE 264
#define G2_BM   128
#define G2_BN   128
#define B_BUF_ELEMS (G2_BN * ASTRIDE)
#define G2_SMEM ((G2_BM + 2 * G2_BN) * ASTRIDE * 2)   // 202752 bytes dynamic
#define NT_CNT  (C_N / G2_BN)                          // 32

__global__ __launch_bounds__(256, 1) void gemm2_tc_kernel() {
    extern __shared__ __align__(16) __nv_bfloat16 sm[];
    __nv_bfloat16* As  = sm;                       // [128][264]
    __nv_bfloat16* Bs0 = sm + G2_BM * ASTRIDE;     // 2 x [128][264]
    __shared__ uint32_t s_rowkey[G2_BM];
    __shared__ int      s_cnt[G2_BM];
    __shared__ uint16_t s_cand[G2_BM][CAND_MAX];

    int tid  = threadIdx.x;
    int lane = tid & 31;
    int wid  = tid >> 5;
    int q    = lane >> 2;
    int tig  = lane & 3;
    int wm   = wid & 3;
    int wn   = wid >> 2;
    int row0 = blockIdx.x * G2_BM;

    if (tid < G2_BM) { s_rowkey[tid] = 0xFFFFFFFFu; s_cnt[tid] = 0; }

    // stage resident A
    #pragma unroll
    for (int i = 0; i < 16; i++) {
        int id  = (i << 8) + tid;
        int row = id >> 5;
        int k8  = (id & 31) << 3;
        *(uint4*)(As + row * ASTRIDE + k8) =
            *(const uint4*)(g_Tb + (size_t)(row0 + row) * Q_N + k8);
    }

    uint32_t bsb[2];
    bsb[0] = (uint32_t)__cvta_generic_to_shared(Bs0);
    bsb[1] = (uint32_t)__cvta_generic_to_shared(Bs0 + B_BUF_ELEMS);

    int g = lane >> 3, idx = lane & 7;
    uint32_t aaddr[2], baddr[2][4];
    #pragma unroll
    for (int i = 0; i < 2; i++) {
        int r = wm * 32 + i * 16 + ((g & 1) << 3) + idx;
        aaddr[i] = (uint32_t)__cvta_generic_to_shared(As + r * ASTRIDE + ((g >> 1) << 3));
    }
    #pragma unroll
    for (int p = 0; p < 2; p++)
        #pragma unroll
        for (int jp = 0; jp < 4; jp++) {
            int r = wn * 64 + jp * 16 + ((g >> 1) << 3) + idx;
            baddr[p][jp] = bsb[p] + (uint32_t)((r * ASTRIDE + ((g & 1) << 3)) * 2);
        }

    #define ISSUE_B(nt_, p_)                                                        \
        do {                                                                        \
            const __nv_bfloat16* src = g_CBb + (size_t)((nt_) * G2_BN) * Q_N;       \
            _Pragma("unroll")                                                       \
            for (int i_ = 0; i_ < 16; i_++) {                                       \
                int id_  = (i_ << 8) + tid;                                         \
                int row_ = id_ >> 5;                                                \
                int k8_  = (id_ & 31) << 3;                                         \
                cp_async16(bsb[p_] + (uint32_t)((row_ * ASTRIDE + k8_) * 2),        \
                           src + (size_t)row_ * Q_N + k8_);                         \
            }                                                                       \
        } while (0)

    ISSUE_B(0, 0); CP_COMMIT();
    ISSUE_B(1, 1); CP_COMMIT();

    int lr[2][2];
    #pragma unroll
    for (int i = 0; i < 2; i++) {
        lr[i][0] = wm * 32 + i * 16 + q;
        lr[i][1] = lr[i][0] + 8;
    }

    for (int nt = 0; nt < NT_CNT; nt++) {
        int p = nt & 1;
        CP_WAIT1();          // own slices of buffer p complete
        __syncthreads();     // everyone's slices complete (also A/init on nt==0)

        float d[2][8][4];
        #pragma unroll
        for (int i = 0; i < 2; i++)
            #pragma unroll
            for (int j = 0; j < 8; j++)
                #pragma unroll
                for (int e = 0; e < 4; e++) d[i][j][e] = 0.f;

        #pragma unroll
        for (int ks = 0; ks < 16; ks++) {
            uint32_t koff = (uint32_t)(ks * 16 * 2);
            uint32_t a[2][4], b[4][4];
            ldsm_x4(a[0], aaddr[0] + koff);
            ldsm_x4(a[1], aaddr[1] + koff);
            #pragma unroll
            for (int jp = 0; jp < 4; jp++) ldsm_x4(b[jp], baddr[p][jp] + koff);
            #pragma unroll
            for (int i = 0; i < 2; i++)
                #pragma unroll
                for (int jp = 0; jp < 4; jp++) {
                    mma16816(d[i][jp * 2 + 0], a[i], &b[jp][0]);
                    mma16816(d[i][jp * 2 + 1], a[i], &b[jp][2]);
                }
        }

        // epilogue phase 1: per-row local min -> shared atomicMin
        int cbase = nt * G2_BN + wn * 64;
        float cq[8][2];
        #pragma unroll
        for (int j = 0; j < 8; j++) {
            cq[j][0] = g_cbsq[cbase + j * 8 + tig * 2];
            cq[j][1] = g_cbsq[cbase + j * 8 + tig * 2 + 1];
        }
        float lmin[2][2] = {{3.4e38f, 3.4e38f}, {3.4e38f, 3.4e38f}};
        #pragma unroll
        for (int i = 0; i < 2; i++)
            #pragma unroll
            for (int j = 0; j < 8; j++) {
                float s00 = fmaf(-2.f, d[i][j][0], cq[j][0]);
                float s01 = fmaf(-2.f, d[i][j][1], cq[j][1]);
                float s10 = fmaf(-2.f, d[i][j][2], cq[j][0]);
                float s11 = fmaf(-2.f, d[i][j][3], cq[j][1]);
                lmin[i][0] = fminf(lmin[i][0], fminf(s00, s01));
                lmin[i][1] = fminf(lmin[i][1], fminf(s10, s11));
            }
        #pragma unroll
        for (int i = 0; i < 2; i++) {
            atomicMin(&s_rowkey[lr[i][0]], fkey(lmin[i][0]));
            atomicMin(&s_rowkey[lr[i][1]], fkey(lmin[i][1]));
        }
        __syncthreads();     // mins folded; all warps done reading buffer p

        // issue B(nt+2) into buffer p NOW (overlaps with register-only phase 2)
        if (nt + 2 < NT_CNT) ISSUE_B(nt + 2, p);
        CP_COMMIT();

        // epilogue phase 2: insert candidates vs tightened threshold (regs only)
        #pragma unroll
        for (int i = 0; i < 2; i++)
            #pragma unroll
            for (int h = 0; h < 2; h++) {
                float thr = funkey(s_rowkey[lr[i][h]]) + RESCUE_DELTA;
                #pragma unroll
                for (int j = 0; j < 8; j++) {
                    float sa = fmaf(-2.f, d[i][j][h * 2 + 0], cq[j][0]);
                    float sb = fmaf(-2.f, d[i][j][h * 2 + 1], cq[j][1]);
                    int c = cbase + j * 8 + tig * 2;
                    if (sa <= thr) {
                        int pos = atomicAdd(&s_cnt[lr[i][h]], 1);
                        if (pos < CAND_MAX) s_cand[lr[i][h]][pos] = (uint16_t)c;
                    }
                    if (sb <= thr) {
                        int pos = atomicAdd(&s_cnt[lr[i][h]], 1);
                        if (pos < CAND_MAX) s_cand[lr[i][h]][pos] = (uint16_t)(c + 1);
                    }
                }
            }
    }

    __syncthreads();
    if (tid < G2_BM) {
        g_ncand[row0 + tid] = s_cnt[tid];
        #pragma unroll
        for (int i = 0; i < CAND_MAX / 8; i++)
            *(uint4*)&g_cand[row0 + tid][i * 8] = *(uint4*)&s_cand[tid][i * 8];
    }
}

// ---------------- kernel 3: exact rescue over candidates (U rows, coalesced) ----------------
__global__ __launch_bounds__(256) void rescue_kernel(const float* __restrict__ X,
                                                     float* __restrict__ out) {
    int wid  = threadIdx.x >> 5;
    int lane = threadIdx.x & 31;
    int row  = blockIdx.x * 8 + wid;

    const float* xrow = X + (size_t)row * D_K;
    float x[32];
    #pragma unroll
    for (int t = 0; t < 32; t++) x[t] = xrow[lane + t * 32];

    float bestv = 3.4e38f;
    int   besti = C_N;
    int n = g_ncand[row];

    if (n <= CAND_MAX) {
        for (int i = 0; i < n; i++) {
            int c = g_cand[row][i];
            const float* urow = g_U + (size_t)c * D_K;
            float part = 0.f;
            #pragma unroll 8
            for (int t = 0; t < 32; t++)
                part = fmaf(x[t], urow[lane + t * 32], part);
            #pragma unroll
            for (int off = 16; off > 0; off >>= 1)
                part += __shfl_xor_sync(0xffffffffu, part, off);
            float sc = fmaf(-2.f, part, g_cbsq[c]);
            if (sc < bestv || (sc == bestv && c < besti)) { bestv = sc; besti = c; }
        }
    } else {
        for (int c = 0; c < C_N; c++) {
            const float* urow = g_U + (size_t)c * D_K;
            float part = 0.f;
            #pragma unroll 8
            for (int t = 0; t < 32; t++)
                part = fmaf(x[t], urow[lane + t * 32], part);
            #pragma unroll
            for (int off = 16; off > 0; off >>= 1)
                part += __shfl_xor_sync(0xffffffffu, part, off);
            float sc = fmaf(-2.f, part, g_cbsq[c]);
            if (sc < bestv) { bestv = sc; besti = c; }
        }
    }
    if (lane == 0) out[row] = (float)besti;
}

// ---------------- launch ----------------
extern "C" void kernel_launch(void* const* d_in, const int* in_sizes, int n_in,
                              void* d_out, int out_size) {
    (void)out_size;
    const float* X  = 0;
    const float* W  = 0;
    const float* CB = 0;
    for (int i = 0; i < n_in; i++) {
        long long s = (long long)in_sizes[i];
        if      (s == (long long)M_TOTAL * D_K) X  = (const float*)d_in[i];
        else if (s == (long long)Q_N * D_K)     W  = (const float*)d_in[i];
        else if (s == (long long)Q_N * C_N)     CB = (const float*)d_in[i];
    }
    if (!X)  X  = (const float*)d_in[0];
    if (!W  && n_in > 2) W  = (const float*)d_in[2];
    if (!CB && n_in > 3) CB = (const float*)d_in[3];

    float* out = (float*)d_out;

    cudaFuncSetAttribute(gemm2_tc_kernel,
                         cudaFuncAttributeMaxDynamicSharedMemorySize, G2_SMEM);

    prep_kernel<<<64 + 4096 + 256, 256>>>(CB, W);
    ugemm_kernel<<<dim3(C_N / 128, D_K / 64), 256>>>(CB, W);
    gemm1b_kernel<<<dim3(M_TOTAL / 128, Q_N / 128), 256>>>(X);
    gemm2_tc_kernel<<<M_TOTAL / G2_BM, 256, G2_SMEM>>>();
    rescue_kernel<<<M_TOTAL / 8, 256>>>(X, out);
}

// round 12
// speedup vs baseline: 4.1480x; 1.0315x over previous
#include <cuda_runtime.h>
#include <cuda_bf16.h>
#include <cstdint>

// Problem constants (fixed shapes from reference)
#define M_TOTAL 16384   // B*L
#define D_K     1024    // D
#define Q_N     256     // Q
#define C_N     4096    // C

#define CAND_MAX 32
#define RESCUE_DELTA 6.0f

// Scratch (device globals: allowed; no allocation APIs)
__device__ float          g_cbsq[C_N];            // ||codebook[:,c]||^2 (fp32 exact)
__device__ __nv_bfloat16  g_Wb[Q_N * D_K];        // bf16 W (512KB)
__device__ __nv_bfloat16  g_Tb[M_TOTAL * Q_N];    // bf16 targets (8MB)
__device__ __nv_bfloat16  g_CBb[C_N * Q_N];       // bf16 codebook, [c][k] (2MB)
__device__ float          g_U[(size_t)C_N * D_K]; // U[c][d] = sum_q CB[q][c] W[q][d] (16MB)
__device__ int            g_ncand[M_TOTAL];
__device__ uint16_t       g_cand[M_TOTAL][CAND_MAX];

// ---------------- packed fp32x2 helpers (FFMA2, validated R5/R7) ----------------
__device__ __forceinline__ void fma2(unsigned long long& d,
                                     unsigned long long a,
                                     unsigned long long b) {
    asm("fma.rn.f32x2 %0, %1, %2, %0;" : "+l"(d) : "l"(a), "l"(b));
}
__device__ __forceinline__ unsigned long long pack2(float x) {
    unsigned long long r;
    unsigned u = __float_as_uint(x);
    asm("mov.b64 %0, {%1, %2};" : "=l"(r) : "r"(u), "r"(u));
    return r;
}
__device__ __forceinline__ float lo32(unsigned long long v) {
    return __uint_as_float((unsigned)(v & 0xffffffffull));
}
__device__ __forceinline__ float hi32(unsigned long long v) {
    return __uint_as_float((unsigned)(v >> 32));
}

// ---------------- warp MMA + ldmatrix + cp.async ----------------
__device__ __forceinline__ void mma16816(float* d, const uint32_t* a, const uint32_t* b) {
    asm volatile(
        "mma.sync.aligned.m16n8k16.row.col.f32.bf16.bf16.f32 "
        "{%0,%1,%2,%3}, {%4,%5,%6,%7}, {%8,%9}, {%0,%1,%2,%3};"
        : "+f"(d[0]), "+f"(d[1]), "+f"(d[2]), "+f"(d[3])
        : "r"(a[0]), "r"(a[1]), "r"(a[2]), "r"(a[3]), "r"(b[0]), "r"(b[1]));
}
__device__ __forceinline__ void ldsm_x4(uint32_t* r, uint32_t addr) {
    asm volatile("ldmatrix.sync.aligned.m8n8.x4.shared.b16 {%0,%1,%2,%3}, [%4];"
                 : "=r"(r[0]), "=r"(r[1]), "=r"(r[2]), "=r"(r[3]) : "r"(addr));
}
__device__ __forceinline__ void cp_async16(uint32_t dst, const void* src) {
    asm volatile("cp.async.cg.shared.global [%0], [%1], 16;" :: "r"(dst), "l"(src));
}
#define CP_COMMIT() asm volatile("cp.async.commit_group;" ::: "memory")
#define CP_WAIT1()  asm volatile("cp.async.wait_group 1;" ::: "memory")

// order-preserving float<->uint key (for atomicMin on scores of any sign)
__device__ __forceinline__ uint32_t fkey(float f) {
    uint32_t b = __float_as_uint(f);
    return (b & 0x80000000u) ? ~b : (b | 0x80000000u);
}
__device__ __forceinline__ float funkey(uint32_t k) {
    uint32_t b = (k & 0x80000000u) ? (k & 0x7FFFFFFFu) : ~k;
    return __uint_as_float(b);
}

// ---------------- prep kernel: cbsq + convCB + convW fused (validated R11) ----------------
__global__ __launch_bounds__(256) void prep_kernel(const float* __restrict__ CB,
                                                   const float* __restrict__ W) {
    __shared__ float red[4][64];
    int b = blockIdx.x;
    int t = threadIdx.x;
    if (b < 64) {
        int c = b * 64 + (t & 63);
        int part = t >> 6;
        float s = 0.f;
        #pragma unroll 8
        for (int k = part * 64; k < part * 64 + 64; k++) {
            float v = CB[(size_t)k * C_N + c];
            s = fmaf(v, v, s);
        }
        red[part][t & 63] = s;
        __syncthreads();
        if (t < 64)
            g_cbsq[b * 64 + t] = red[0][t] + red[1][t] + red[2][t] + red[3][t];
    } else if (b < 64 + 4096) {
        int o = (b - 64) * 256 + t;
        int k = o & 255;
        int c = o >> 8;
        g_CBb[o] = __float2bfloat16(CB[(size_t)k * C_N + c]);
    } else {
        int idx = (b - 4160) * 256 + t;
        float4 v = ((const float4*)W)[idx];
        __nv_bfloat162* o = (__nv_bfloat162*)g_Wb + idx * 2;
        o[0] = __nv_bfloat162(__float2bfloat16(v.x), __float2bfloat16(v.y));
        o[1] = __nv_bfloat162(__float2bfloat16(v.z), __float2bfloat16(v.w));
    }
}

// ---------------- kernel U: U = CB^T @ W  (fp32 FFMA2, 8x4 microtile, validated R11) ----------------
__global__ __launch_bounds__(256) void ugemm_kernel(const float* __restrict__ CB,
                                                    const float* __restrict__ W) {
    __shared__ __align__(16) float As[32][128];
    __shared__ __align__(16) float Bs[32][64];
    int tid = threadIdx.x;
    int tr = tid >> 4;
    int tc = tid & 15;
    int row0 = blockIdx.x << 7;   // c
    int col0 = blockIdx.y << 6;   // d

    unsigned long long acc[4][4];
    #pragma unroll
    for (int p = 0; p < 4; p++)
        #pragma unroll
        for (int j = 0; j < 4; j++) acc[p][j] = 0ull;

    for (int kc = 0; kc < Q_N; kc += 32) {
        __syncthreads();
        #pragma unroll
        for (int i = 0; i < 4; i++) {
            int f4 = (i << 8) + tid;
            int q  = f4 >> 5;
            int e4 = (f4 & 31) << 2;
            *(float4*)&As[q][e4] = *(const float4*)(CB + (size_t)(kc + q) * C_N + row0 + e4);
        }
        #pragma unroll
        for (int i = 0; i < 2; i++) {
            int f4 = (i << 8) + tid;
            int q  = f4 >> 4;
            int e4 = (f4 & 15) << 2;
            *(float4*)&Bs[q][e4] = *(const float4*)(W + (size_t)(kc + q) * D_K + col0 + e4);
        }
        __syncthreads();
        #pragma unroll
        for (int k = 0; k < 32; k++) {
            ulonglong2 a01 = *(const ulonglong2*)&As[k][tr << 3];
            ulonglong2 a23 = *(const ulonglong2*)&As[k][(tr << 3) + 4];
            float4 b = *(const float4*)&Bs[k][tc << 2];
            unsigned long long bb0 = pack2(b.x), bb1 = pack2(b.y);
            unsigned long long bb2 = pack2(b.z), bb3 = pack2(b.w);
            fma2(acc[0][0], a01.x, bb0); fma2(acc[0][1], a01.x, bb1);
            fma2(acc[0][2], a01.x, bb2); fma2(acc[0][3], a01.x, bb3);
            fma2(acc[1][0], a01.y, bb0); fma2(acc[1][1], a01.y, bb1);
            fma2(acc[1][2], a01.y, bb2); fma2(acc[1][3], a01.y, bb3);
            fma2(acc[2][0], a23.x, bb0); fma2(acc[2][1], a23.x, bb1);
            fma2(acc[2][2], a23.x, bb2); fma2(acc[2][3], a23.x, bb3);
            fma2(acc[3][0], a23.y, bb0); fma2(acc[3][1], a23.y, bb1);
            fma2(acc[3][2], a23.y, bb2); fma2(acc[3][3], a23.y, bb3);
        }
    }
    #pragma unroll
    for (int p = 0; p < 4; p++) {
        int c = row0 + (tr << 3) + (p << 1);
        #pragma unroll
        for (int j = 0; j < 4; j++) {
            int d = col0 + (tc << 2) + j;
            g_U[(size_t)c       * D_K + d] = lo32(acc[p][j]);
            g_U[(size_t)(c + 1) * D_K + d] = hi32(acc[p][j]);
        }
    }
}

// ---------------- kernel 1: T~ = bf16(X) @ bf16(W)^T  (validated R10/R11) ----------------
#define T_STRIDE 72
__global__ __launch_bounds__(256, 2) void gemm1b_kernel(const float* __restrict__ X) {
    __shared__ __align__(16) __nv_bfloat16 As[128][T_STRIDE];
    __shared__ __align__(16) __nv_bfloat16 Bs[128][T_STRIDE];

    int tid  = threadIdx.x;
    int wid  = tid >> 5;
    int lane = tid & 31;
    int q    = lane >> 2;
    int tig  = lane & 3;
    int wm   = wid & 3;
    int wn   = wid >> 2;
    int row0 = blockIdx.x << 7;
    int col0 = blockIdx.y << 7;

    int g   = lane >> 3, idx = lane & 7;
    uint32_t aaddr[2], baddr[4];
    #pragma unroll
    for (int i = 0; i < 2; i++) {
        int r = wm * 32 + i * 16 + ((g & 1) << 3) + idx;
        aaddr[i] = (uint32_t)__cvta_generic_to_shared(&As[r][(g >> 1) << 3]);
    }
    #pragma unroll
    for (int jp = 0; jp < 4; jp++) {
        int r = wn * 64 + jp * 16 + ((g >> 1) << 3) + idx;
        baddr[jp] = (uint32_t)__cvta_generic_to_shared(&Bs[r][(g & 1) << 3]);
    }

    float d[2][8][4];
    #pragma unroll
    for (int i = 0; i < 2; i++)
        #pragma unroll
        for (int j = 0; j < 8; j++)
            #pragma unroll
            for (int e = 0; e < 4; e++) d[i][j][e] = 0.f;

    for (int kc = 0; kc < D_K; kc += 64) {
        __syncthreads();
        #pragma unroll
        for (int i = 0; i < 8; i++) {
            int fi  = (i << 8) + tid;
            int row = fi >> 4;
            int c4  = (fi & 15) << 2;
            float4 v = *(const float4*)(X + (size_t)(row0 + row) * D_K + kc + c4);
            *(__nv_bfloat162*)&As[row][c4] =
                __nv_bfloat162(__float2bfloat16(v.x), __float2bfloat16(v.y));
            *(__nv_bfloat162*)&As[row][c4 + 2] =
                __nv_bfloat162(__float2bfloat16(v.z), __float2bfloat16(v.w));
        }
        #pragma unroll
        for (int i = 0; i < 4; i++) {
            int id  = (i << 8) + tid;
            int row = id >> 3;
            int k8  = (id & 7) << 3;
            *(uint4*)&Bs[row][k8] = *(const uint4*)(g_Wb + (size_t)(col0 + row) * D_K + kc + k8);
        }
        __syncthreads();
        #pragma unroll
        for (int ks = 0; ks < 4; ks++) {
            uint32_t koff = (uint32_t)(ks * 16 * 2);
            uint32_t a[2][4], b[4][4];
            ldsm_x4(a[0], aaddr[0] + koff);
            ldsm_x4(a[1], aaddr[1] + koff);
            #pragma unroll
            for (int jp = 0; jp < 4; jp++) ldsm_x4(b[jp], baddr[jp] + koff);
            #pragma unroll
            for (int i = 0; i < 2; i++)
                #pragma unroll
                for (int jp = 0; jp < 4; jp++) {
                    mma16816(d[i][jp * 2 + 0], a[i], &b[jp][0]);
                    mma16816(d[i][jp * 2 + 1], a[i], &b[jp][2]);
                }
        }
    }
    #pragma unroll
    for (int j = 0; j < 8; j++) {
        int c = col0 + wn * 64 + j * 8 + tig * 2;
        #pragma unroll
        for (int i = 0; i < 2; i++) {
            int r = row0 + wm * 32 + i * 16 + q;
            *(__nv_bfloat162*)(g_Tb + (size_t)r * Q_N + c) =
                __nv_bfloat162(__float2bfloat16(d[i][j][0]), __float2bfloat16(d[i][j][1]));
            *(__nv_bfloat162*)(g_Tb + (size_t)(r + 8) * Q_N + c) =
                __nv_bfloat162(__float2bfloat16(d[i][j][2]), __float2bfloat16(d[i][j][3]));
        }
    }
}

// ---------------- kernel 2: filter GEMM, 512 threads (16 warps, 4m x 4n) ----------------
#define ASTRIDE 264
#define G2_BM   128
#define G2_BN   128
#define G2_THREADS 512
#define B_BUF_ELEMS (G2_BN * ASTRIDE)
#define G2_SMEM ((G2_BM + 2 * G2_BN) * ASTRIDE * 2)   // 202752 bytes dynamic
#define NT_CNT  (C_N / G2_BN)                          // 32

__global__ __launch_bounds__(G2_THREADS, 1) void gemm2_tc_kernel() {
    extern __shared__ __align__(16) __nv_bfloat16 sm[];
    __nv_bfloat16* As  = sm;                       // [128][264]
    __nv_bfloat16* Bs0 = sm + G2_BM * ASTRIDE;     // 2 x [128][264]
    __shared__ uint32_t s_rowkey[G2_BM];
    __shared__ int      s_cnt[G2_BM];
    __shared__ uint16_t s_cand[G2_BM][CAND_MAX];

    int tid  = threadIdx.x;
    int lane = tid & 31;
    int wid  = tid >> 5;       // 0..15
    int q    = lane >> 2;
    int tig  = lane & 3;
    int wm   = wid & 3;        // rows wm*32..+31
    int wn   = wid >> 2;       // cols wn*32..+31 within 128-chunk
    int row0 = blockIdx.x * G2_BM;

    if (tid < G2_BM) { s_rowkey[tid] = 0xFFFFFFFFu; s_cnt[tid] = 0; }

    // stage resident A: 4096 uint4 / 512 threads = 8 each
    #pragma unroll
    for (int i = 0; i < 8; i++) {
        int id  = (i << 9) + tid;
        int row = id >> 5;
        int k8  = (id & 31) << 3;
        *(uint4*)(As + row * ASTRIDE + k8) =
            *(const uint4*)(g_Tb + (size_t)(row0 + row) * Q_N + k8);
    }

    uint32_t bsb[2];
    bsb[0] = (uint32_t)__cvta_generic_to_shared(Bs0);
    bsb[1] = (uint32_t)__cvta_generic_to_shared(Bs0 + B_BUF_ELEMS);

    int g = lane >> 3, idx = lane & 7;
    uint32_t aaddr[2], baddr[2][2];
    #pragma unroll
    for (int i = 0; i < 2; i++) {
        int r = wm * 32 + i * 16 + ((g & 1) << 3) + idx;
        aaddr[i] = (uint32_t)__cvta_generic_to_shared(As + r * ASTRIDE + ((g >> 1) << 3));
    }
    #pragma unroll
    for (int p = 0; p < 2; p++)
        #pragma unroll
        for (int jp = 0; jp < 2; jp++) {
            int r = wn * 32 + jp * 16 + ((g >> 1) << 3) + idx;
            baddr[p][jp] = bsb[p] + (uint32_t)((r * ASTRIDE + ((g & 1) << 3)) * 2);
        }

    // cp.async B staging: 4096 uint4 per chunk / 512 threads = 8 each
    #define ISSUE_B(nt_, p_)                                                        \
        do {                                                                        \
            const __nv_bfloat16* src = g_CBb + (size_t)((nt_) * G2_BN) * Q_N;       \
            _Pragma("unroll")                                                       \
            for (int i_ = 0; i_ < 8; i_++) {                                        \
                int id_  = (i_ << 9) + tid;                                         \
                int row_ = id_ >> 5;                                                \
                int k8_  = (id_ & 31) << 3;                                         \
                cp_async16(bsb[p_] + (uint32_t)((row_ * ASTRIDE + k8_) * 2),        \
                           src + (size_t)row_ * Q_N + k8_);                         \
            }                                                                       \
        } while (0)

    ISSUE_B(0, 0); CP_COMMIT();
    ISSUE_B(1, 1); CP_COMMIT();

    int lr[2][2];
    #pragma unroll
    for (int i = 0; i < 2; i++) {
        lr[i][0] = wm * 32 + i * 16 + q;
        lr[i][1] = lr[i][0] + 8;
    }

    for (int nt = 0; nt < NT_CNT; nt++) {
        int p = nt & 1;
        CP_WAIT1();
        __syncthreads();

        float d[2][4][4];
        #pragma unroll
        for (int i = 0; i < 2; i++)
            #pragma unroll
            for (int j = 0; j < 4; j++)
                #pragma unroll
                for (int e = 0; e < 4; e++) d[i][j][e] = 0.f;

        #pragma unroll
        for (int ks = 0; ks < 16; ks++) {
            uint32_t koff = (uint32_t)(ks * 16 * 2);
            uint32_t a[2][4], b[2][4];
            ldsm_x4(a[0], aaddr[0] + koff);
            ldsm_x4(a[1], aaddr[1] + koff);
            ldsm_x4(b[0], baddr[p][0] + koff);
            ldsm_x4(b[1], baddr[p][1] + koff);
            #pragma unroll
            for (int i = 0; i < 2; i++) {
                mma16816(d[i][0], a[i], &b[0][0]);
                mma16816(d[i][1], a[i], &b[0][2]);
                mma16816(d[i][2], a[i], &b[1][0]);
                mma16816(d[i][3], a[i], &b[1][2]);
            }
        }

        // epilogue phase 1: per-row local min -> shared atomicMin
        int cbase = nt * G2_BN + wn * 32;
        float cq[4][2];
        #pragma unroll
        for (int j = 0; j < 4; j++) {
            cq[j][0] = g_cbsq[cbase + j * 8 + tig * 2];
            cq[j][1] = g_cbsq[cbase + j * 8 + tig * 2 + 1];
        }
        float lmin[2][2] = {{3.4e38f, 3.4e38f}, {3.4e38f, 3.4e38f}};
        #pragma unroll
        for (int i = 0; i < 2; i++)
            #pragma unroll
            for (int j = 0; j < 4; j++) {
                float s00 = fmaf(-2.f, d[i][j][0], cq[j][0]);
                float s01 = fmaf(-2.f, d[i][j][1], cq[j][1]);
                float s10 = fmaf(-2.f, d[i][j][2], cq[j][0]);
                float s11 = fmaf(-2.f, d[i][j][3], cq[j][1]);
                lmin[i][0] = fminf(lmin[i][0], fminf(s00, s01));
                lmin[i][1] = fminf(lmin[i][1], fminf(s10, s11));
            }
        #pragma unroll
        for (int i = 0; i < 2; i++) {
            atomicMin(&s_rowkey[lr[i][0]], fkey(lmin[i][0]));
            atomicMin(&s_rowkey[lr[i][1]], fkey(lmin[i][1]));
        }
        __syncthreads();     // mins folded; all warps done reading buffer p

        // issue B(nt+2) into buffer p (overlaps with register-only phase 2)
        if (nt + 2 < NT_CNT) ISSUE_B(nt + 2, p);
        CP_COMMIT();

        // epilogue phase 2: insert candidates vs tightened threshold
        #pragma unroll
        for (int i = 0; i < 2; i++)
            #pragma unroll
            for (int h = 0; h < 2; h++) {
                float thr = funkey(s_rowkey[lr[i][h]]) + RESCUE_DELTA;
                #pragma unroll
                for (int j = 0; j < 4; j++) {
                    float sa = fmaf(-2.f, d[i][j][h * 2 + 0], cq[j][0]);
                    float sb = fmaf(-2.f, d[i][j][h * 2 + 1], cq[j][1]);
                    int c = cbase + j * 8 + tig * 2;
                    if (sa <= thr) {
                        int pos = atomicAdd(&s_cnt[lr[i][h]], 1);
                        if (pos < CAND_MAX) s_cand[lr[i][h]][pos] = (uint16_t)c;
                    }
                    if (sb <= thr) {
                        int pos = atomicAdd(&s_cnt[lr[i][h]], 1);
                        if (pos < CAND_MAX) s_cand[lr[i][h]][pos] = (uint16_t)(c + 1);
                    }
                }
            }
    }

    __syncthreads();
    if (tid < G2_BM) {
        g_ncand[row0 + tid] = s_cnt[tid];
        #pragma unroll
        for (int i = 0; i < CAND_MAX / 8; i++)
            *(uint4*)&g_cand[row0 + tid][i * 8] = *(uint4*)&s_cand[tid][i * 8];
    }
}

// ---------------- kernel 3: exact rescue over candidates (validated R9-R11) ----------------
__global__ __launch_bounds__(256) void rescue_kernel(const float* __restrict__ X,
                                                     float* __restrict__ out) {
    int wid  = threadIdx.x >> 5;
    int lane = threadIdx.x & 31;
    int row  = blockIdx.x * 8 + wid;

    const float* xrow = X + (size_t)row * D_K;
    float x[32];
    #pragma unroll
    for (int t = 0; t < 32; t++) x[t] = xrow[lane + t * 32];

    float bestv = 3.4e38f;
    int   besti = C_N;
    int n = g_ncand[row];

    if (n <= CAND_MAX) {
        for (int i = 0; i < n; i++) {
            int c = g_cand[row][i];
            const float* urow = g_U + (size_t)c * D_K;
            float part = 0.f;
            #pragma unroll 8
            for (int t = 0; t < 32; t++)
                part = fmaf(x[t], urow[lane + t * 32], part);
            #pragma unroll
            for (int off = 16; off > 0; off >>= 1)
                part += __shfl_xor_sync(0xffffffffu, part, off);
            float sc = fmaf(-2.f, part, g_cbsq[c]);
            if (sc < bestv || (sc == bestv && c < besti)) { bestv = sc; besti = c; }
        }
    } else {
        for (int c = 0; c < C_N; c++) {
            const float* urow = g_U + (size_t)c * D_K;
            float part = 0.f;
            #pragma unroll 8
            for (int t = 0; t < 32; t++)
                part = fmaf(x[t], urow[lane + t * 32], part);
            #pragma unroll
            for (int off = 16; off > 0; off >>= 1)
                part += __shfl_xor_sync(0xffffffffu, part, off);
            float sc = fmaf(-2.f, part, g_cbsq[c]);
            if (sc < bestv) { bestv = sc; besti = c; }
        }
    }
    if (lane == 0) out[row] = (float)besti;
}

// ---------------- launch ----------------
extern "C" void kernel_launch(void* const* d_in, const int* in_sizes, int n_in,
                              void* d_out, int out_size) {
    (void)out_size;
    const float* X  = 0;
    const float* W  = 0;
    const float* CB = 0;
    for (int i = 0; i < n_in; i++) {
        long long s = (long long)in_sizes[i];
        if      (s == (long long)M_TOTAL * D_K) X  = (const float*)d_in[i];
        else if (s == (long long)Q_N * D_K)     W  = (const float*)d_in[i];
        else if (s == (long long)Q_N * C_N)     CB = (const float*)d_in[i];
    }
    if (!X)  X  = (const float*)d_in[0];
    if (!W  && n_in > 2) W  = (const float*)d_in[2];
    if (!CB && n_in > 3) CB = (const float*)d_in[3];

    float* out = (float*)d_out;

    cudaFuncSetAttribute(gemm2_tc_kernel,
                         cudaFuncAttributeMaxDynamicSharedMemorySize, G2_SMEM);

    prep_kernel<<<64 + 4096 + 256, 256>>>(CB, W);
    ugemm_kernel<<<dim3(C_N / 128, D_K / 64), 256>>>(CB, W);
    gemm1b_kernel<<<dim3(M_TOTAL / 128, Q_N / 128), 256>>>(X);
    gemm2_tc_kernel<<<M_TOTAL / G2_BM, G2_THREADS, G2_SMEM>>>();
    rescue_kernel<<<M_TOTAL / 8, 256>>>(X, out);
}

// round 13
// speedup vs baseline: 4.1977x; 1.0120x over previous
#include <cuda_runtime.h>
#include <cuda_bf16.h>
#include <cstdint>

// Problem constants (fixed shapes from reference)
#define M_TOTAL 16384   // B*L
#define D_K     1024    // D
#define Q_N     256     // Q
#define C_N     4096    // C

#define CAND_MAX 32
#define RESCUE_DELTA 6.0f

// Scratch (device globals: allowed; no allocation APIs)
__device__ float          g_cbsq[C_N];            // ||codebook[:,c]||^2 (fp32 exact)
__device__ __nv_bfloat16  g_Wb[Q_N * D_K];        // bf16 W (512KB)
__device__ __nv_bfloat16  g_Tb[M_TOTAL * Q_N];    // bf16 targets (8MB)
__device__ __nv_bfloat16  g_CBb[C_N * Q_N];       // bf16 codebook, [c][k] (2MB)
__device__ float          g_U[(size_t)C_N * D_K]; // U[c][d] = sum_q CB[q][c] W[q][d] (16MB)
__device__ int            g_ncand[M_TOTAL];
__device__ uint16_t       g_cand[M_TOTAL][CAND_MAX];

// ---------------- packed fp32x2 helpers (FFMA2, validated R5/R7) ----------------
__device__ __forceinline__ void fma2(unsigned long long& d,
                                     unsigned long long a,
                                     unsigned long long b) {
    asm("fma.rn.f32x2 %0, %1, %2, %0;" : "+l"(d) : "l"(a), "l"(b));
}
__device__ __forceinline__ unsigned long long pack2(float x) {
    unsigned long long r;
    unsigned u = __float_as_uint(x);
    asm("mov.b64 %0, {%1, %2};" : "=l"(r) : "r"(u), "r"(u));
    return r;
}
__device__ __forceinline__ float lo32(unsigned long long v) {
    return __uint_as_float((unsigned)(v & 0xffffffffull));
}
__device__ __forceinline__ float hi32(unsigned long long v) {
    return __uint_as_float((unsigned)(v >> 32));
}

// ---------------- warp MMA + ldmatrix + cp.async ----------------
__device__ __forceinline__ void mma16816(float* d, const uint32_t* a, const uint32_t* b) {
    asm volatile(
        "mma.sync.aligned.m16n8k16.row.col.f32.bf16.bf16.f32 "
        "{%0,%1,%2,%3}, {%4,%5,%6,%7}, {%8,%9}, {%0,%1,%2,%3};"
        : "+f"(d[0]), "+f"(d[1]), "+f"(d[2]), "+f"(d[3])
        : "r"(a[0]), "r"(a[1]), "r"(a[2]), "r"(a[3]), "r"(b[0]), "r"(b[1]));
}
__device__ __forceinline__ void ldsm_x4(uint32_t* r, uint32_t addr) {
    asm volatile("ldmatrix.sync.aligned.m8n8.x4.shared.b16 {%0,%1,%2,%3}, [%4];"
                 : "=r"(r[0]), "=r"(r[1]), "=r"(r[2]), "=r"(r[3]) : "r"(addr));
}
__device__ __forceinline__ void cp_async16(uint32_t dst, const void* src) {
    asm volatile("cp.async.cg.shared.global [%0], [%1], 16;" :: "r"(dst), "l"(src));
}
#define CP_COMMIT() asm volatile("cp.async.commit_group;" ::: "memory")
#define CP_WAIT0()  asm volatile("cp.async.wait_group 0;" ::: "memory")

// order-preserving float<->uint key (for atomicMin on scores of any sign)
__device__ __forceinline__ uint32_t fkey(float f) {
    uint32_t b = __float_as_uint(f);
    return (b & 0x80000000u) ? ~b : (b | 0x80000000u);
}
__device__ __forceinline__ float funkey(uint32_t k) {
    uint32_t b = (k & 0x80000000u) ? (k & 0x7FFFFFFFu) : ~k;
    return __uint_as_float(b);
}

// ---------------- prep kernel: cbsq + convCB + convW fused (validated R11) ----------------
__global__ __launch_bounds__(256) void prep_kernel(const float* __restrict__ CB,
                                                   const float* __restrict__ W) {
    __shared__ float red[4][64];
    int b = blockIdx.x;
    int t = threadIdx.x;
    if (b < 64) {
        int c = b * 64 + (t & 63);
        int part = t >> 6;
        float s = 0.f;
        #pragma unroll 8
        for (int k = part * 64; k < part * 64 + 64; k++) {
            float v = CB[(size_t)k * C_N + c];
            s = fmaf(v, v, s);
        }
        red[part][t & 63] = s;
        __syncthreads();
        if (t < 64)
            g_cbsq[b * 64 + t] = red[0][t] + red[1][t] + red[2][t] + red[3][t];
    } else if (b < 64 + 4096) {
        int o = (b - 64) * 256 + t;
        int k = o & 255;
        int c = o >> 8;
        g_CBb[o] = __float2bfloat16(CB[(size_t)k * C_N + c]);
    } else {
        int idx = (b - 4160) * 256 + t;
        float4 v = ((const float4*)W)[idx];
        __nv_bfloat162* o = (__nv_bfloat162*)g_Wb + idx * 2;
        o[0] = __nv_bfloat162(__float2bfloat16(v.x), __float2bfloat16(v.y));
        o[1] = __nv_bfloat162(__float2bfloat16(v.z), __float2bfloat16(v.w));
    }
}

// ---------------- kernel U: U = CB^T @ W  (fp32 FFMA2, 8x4 microtile, validated R11) ----------------
__global__ __launch_bounds__(256) void ugemm_kernel(const float* __restrict__ CB,
                                                    const float* __restrict__ W) {
    __shared__ __align__(16) float As[32][128];
    __shared__ __align__(16) float Bs[32][64];
    int tid = threadIdx.x;
    int tr = tid >> 4;
    int tc = tid & 15;
    int row0 = blockIdx.x << 7;   // c
    int col0 = blockIdx.y << 6;   // d

    unsigned long long acc[4][4];
    #pragma unroll
    for (int p = 0; p < 4; p++)
        #pragma unroll
        for (int j = 0; j < 4; j++) acc[p][j] = 0ull;

    for (int kc = 0; kc < Q_N; kc += 32) {
        __syncthreads();
        #pragma unroll
        for (int i = 0; i < 4; i++) {
            int f4 = (i << 8) + tid;
            int q  = f4 >> 5;
            int e4 = (f4 & 31) << 2;
            *(float4*)&As[q][e4] = *(const float4*)(CB + (size_t)(kc + q) * C_N + row0 + e4);
        }
        #pragma unroll
        for (int i = 0; i < 2; i++) {
            int f4 = (i << 8) + tid;
            int q  = f4 >> 4;
            int e4 = (f4 & 15) << 2;
            *(float4*)&Bs[q][e4] = *(const float4*)(W + (size_t)(kc + q) * D_K + col0 + e4);
        }
        __syncthreads();
        #pragma unroll
        for (int k = 0; k < 32; k++) {
            ulonglong2 a01 = *(const ulonglong2*)&As[k][tr << 3];
            ulonglong2 a23 = *(const ulonglong2*)&As[k][(tr << 3) + 4];
            float4 b = *(const float4*)&Bs[k][tc << 2];
            unsigned long long bb0 = pack2(b.x), bb1 = pack2(b.y);
            unsigned long long bb2 = pack2(b.z), bb3 = pack2(b.w);
            fma2(acc[0][0], a01.x, bb0); fma2(acc[0][1], a01.x, bb1);
            fma2(acc[0][2], a01.x, bb2); fma2(acc[0][3], a01.x, bb3);
            fma2(acc[1][0], a01.y, bb0); fma2(acc[1][1], a01.y, bb1);
            fma2(acc[1][2], a01.y, bb2); fma2(acc[1][3], a01.y, bb3);
            fma2(acc[2][0], a23.x, bb0); fma2(acc[2][1], a23.x, bb1);
            fma2(acc[2][2], a23.x, bb2); fma2(acc[2][3], a23.x, bb3);
            fma2(acc[3][0], a23.y, bb0); fma2(acc[3][1], a23.y, bb1);
            fma2(acc[3][2], a23.y, bb2); fma2(acc[3][3], a23.y, bb3);
        }
    }
    #pragma unroll
    for (int p = 0; p < 4; p++) {
        int c = row0 + (tr << 3) + (p << 1);
        #pragma unroll
        for (int j = 0; j < 4; j++) {
            int d = col0 + (tc << 2) + j;
            g_U[(size_t)c       * D_K + d] = lo32(acc[p][j]);
            g_U[(size_t)(c + 1) * D_K + d] = hi32(acc[p][j]);
        }
    }
}

// ---------------- kernel 1: T~ = bf16(X) @ bf16(W)^T  (validated R10/R11) ----------------
#define T_STRIDE 72
__global__ __launch_bounds__(256, 2) void gemm1b_kernel(const float* __restrict__ X) {
    __shared__ __align__(16) __nv_bfloat16 As[128][T_STRIDE];
    __shared__ __align__(16) __nv_bfloat16 Bs[128][T_STRIDE];

    int tid  = threadIdx.x;
    int wid  = tid >> 5;
    int lane = tid & 31;
    int q    = lane >> 2;
    int tig  = lane & 3;
    int wm   = wid & 3;
    int wn   = wid >> 2;
    int row0 = blockIdx.x << 7;
    int col0 = blockIdx.y << 7;

    int g   = lane >> 3, idx = lane & 7;
    uint32_t aaddr[2], baddr[4];
    #pragma unroll
    for (int i = 0; i < 2; i++) {
        int r = wm * 32 + i * 16 + ((g & 1) << 3) + idx;
        aaddr[i] = (uint32_t)__cvta_generic_to_shared(&As[r][(g >> 1) << 3]);
    }
    #pragma unroll
    for (int jp = 0; jp < 4; jp++) {
        int r = wn * 64 + jp * 16 + ((g >> 1) << 3) + idx;
        baddr[jp] = (uint32_t)__cvta_generic_to_shared(&Bs[r][(g & 1) << 3]);
    }

    float d[2][8][4];
    #pragma unroll
    for (int i = 0; i < 2; i++)
        #pragma unroll
        for (int j = 0; j < 8; j++)
            #pragma unroll
            for (int e = 0; e < 4; e++) d[i][j][e] = 0.f;

    for (int kc = 0; kc < D_K; kc += 64) {
        __syncthreads();
        #pragma unroll
        for (int i = 0; i < 8; i++) {
            int fi  = (i << 8) + tid;
            int row = fi >> 4;
            int c4  = (fi & 15) << 2;
            float4 v = *(const float4*)(X + (size_t)(row0 + row) * D_K + kc + c4);
            *(__nv_bfloat162*)&As[row][c4] =
                __nv_bfloat162(__float2bfloat16(v.x), __float2bfloat16(v.y));
            *(__nv_bfloat162*)&As[row][c4 + 2] =
                __nv_bfloat162(__float2bfloat16(v.z), __float2bfloat16(v.w));
        }
        #pragma unroll
        for (int i = 0; i < 4; i++) {
            int id  = (i << 8) + tid;
            int row = id >> 3;
            int k8  = (id & 7) << 3;
            *(uint4*)&Bs[row][k8] = *(const uint4*)(g_Wb + (size_t)(col0 + row) * D_K + kc + k8);
        }
        __syncthreads();
        #pragma unroll
        for (int ks = 0; ks < 4; ks++) {
            uint32_t koff = (uint32_t)(ks * 16 * 2);
            uint32_t a[2][4], b[4][4];
            ldsm_x4(a[0], aaddr[0] + koff);
            ldsm_x4(a[1], aaddr[1] + koff);
            #pragma unroll
            for (int jp = 0; jp < 4; jp++) ldsm_x4(b[jp], baddr[jp] + koff);
            #pragma unroll
            for (int i = 0; i < 2; i++)
                #pragma unroll
                for (int jp = 0; jp < 4; jp++) {
                    mma16816(d[i][jp * 2 + 0], a[i], &b[jp][0]);
                    mma16816(d[i][jp * 2 + 1], a[i], &b[jp][2]);
                }
        }
    }
    #pragma unroll
    for (int j = 0; j < 8; j++) {
        int c = col0 + wn * 64 + j * 8 + tig * 2;
        #pragma unroll
        for (int i = 0; i < 2; i++) {
            int r = row0 + wm * 32 + i * 16 + q;
            *(__nv_bfloat162*)(g_Tb + (size_t)r * Q_N + c) =
                __nv_bfloat162(__float2bfloat16(d[i][j][0]), __float2bfloat16(d[i][j][1]));
            *(__nv_bfloat162*)(g_Tb + (size_t)(r + 8) * Q_N + c) =
                __nv_bfloat162(__float2bfloat16(d[i][j][2]), __float2bfloat16(d[i][j][3]));
        }
    }
}

// ---------------- kernel 2: filter GEMM, BM=64, 2 CTAs/SM, single B buffer ----------------
#define ASTRIDE 264
#define G2_BM   64
#define G2_BN   128
#define G2_THREADS 256
#define G2_SMEM ((G2_BM + G2_BN) * ASTRIDE * 2)   // 101376 bytes dynamic
#define NT_CNT  (C_N / G2_BN)                      // 32

__global__ __launch_bounds__(G2_THREADS, 2) void gemm2_tc_kernel() {
    extern __shared__ __align__(16) __nv_bfloat16 sm[];
    __nv_bfloat16* As = sm;                       // [64][264]
    __nv_bfloat16* Bs = sm + G2_BM * ASTRIDE;     // [128][264]
    __shared__ uint32_t s_rowkey[G2_BM];
    __shared__ int      s_cnt[G2_BM];
    __shared__ uint16_t s_cand[G2_BM][CAND_MAX];

    int tid  = threadIdx.x;
    int lane = tid & 31;
    int wid  = tid >> 5;       // 0..7
    int q    = lane >> 2;
    int tig  = lane & 3;
    int wm   = wid & 1;        // rows wm*32..+31
    int wn   = wid >> 1;       // cols wn*32..+31 within 128-chunk
    int row0 = blockIdx.x * G2_BM;

    if (tid < G2_BM) { s_rowkey[tid] = 0xFFFFFFFFu; s_cnt[tid] = 0; }

    // stage resident A: 64 rows x 32 uint4 = 2048 uint4 / 256 threads = 8 each
    #pragma unroll
    for (int i = 0; i < 8; i++) {
        int id  = (i << 8) + tid;
        int row = id >> 5;
        int k8  = (id & 31) << 3;
        *(uint4*)(As + row * ASTRIDE + k8) =
            *(const uint4*)(g_Tb + (size_t)(row0 + row) * Q_N + k8);
    }

    uint32_t bsb = (uint32_t)__cvta_generic_to_shared(Bs);

    int g = lane >> 3, idx = lane & 7;
    uint32_t aaddr[2], baddr[2];
    #pragma unroll
    for (int i = 0; i < 2; i++) {
        int r = wm * 32 + i * 16 + ((g & 1) << 3) + idx;
        aaddr[i] = (uint32_t)__cvta_generic_to_shared(As + r * ASTRIDE + ((g >> 1) << 3));
    }
    #pragma unroll
    for (int jp = 0; jp < 2; jp++) {
        int r = wn * 32 + jp * 16 + ((g >> 1) << 3) + idx;
        baddr[jp] = bsb + (uint32_t)((r * ASTRIDE + ((g & 1) << 3)) * 2);
    }

    // cp.async B staging: 128 rows x 32 uint4 = 4096 uint4 / 256 threads = 16 each
    #define ISSUE_B(nt_)                                                            \
        do {                                                                        \
            const __nv_bfloat16* src = g_CBb + (size_t)((nt_) * G2_BN) * Q_N;       \
            _Pragma("unroll")                                                       \
            for (int i_ = 0; i_ < 16; i_++) {                                       \
                int id_  = (i_ << 8) + tid;                                         \
                int row_ = id_ >> 5;                                                \
                int k8_  = (id_ & 31) << 3;                                         \
                cp_async16(bsb + (uint32_t)((row_ * ASTRIDE + k8_) * 2),            \
                           src + (size_t)row_ * Q_N + k8_);                         \
            }                                                                       \
        } while (0)

    ISSUE_B(0); CP_COMMIT();

    int lr[2][2];
    #pragma unroll
    for (int i = 0; i < 2; i++) {
        lr[i][0] = wm * 32 + i * 16 + q;
        lr[i][1] = lr[i][0] + 8;
    }

    for (int nt = 0; nt < NT_CNT; nt++) {
        CP_WAIT0();
        __syncthreads();     // B(nt) staged; also covers A/init on nt==0

        float d[2][4][4];
        #pragma unroll
        for (int i = 0; i < 2; i++)
            #pragma unroll
            for (int j = 0; j < 4; j++)
                #pragma unroll
                for (int e = 0; e < 4; e++) d[i][j][e] = 0.f;

        #pragma unroll
        for (int ks = 0; ks < 16; ks++) {
            uint32_t koff = (uint32_t)(ks * 16 * 2);
            uint32_t a[2][4], b[2][4];
            ldsm_x4(a[0], aaddr[0] + koff);
            ldsm_x4(a[1], aaddr[1] + koff);
            ldsm_x4(b[0], baddr[0] + koff);
            ldsm_x4(b[1], baddr[1] + koff);
            #pragma unroll
            for (int i = 0; i < 2; i++) {
                mma16816(d[i][0], a[i], &b[0][0]);
                mma16816(d[i][1], a[i], &b[0][2]);
                mma16816(d[i][2], a[i], &b[1][0]);
                mma16816(d[i][3], a[i], &b[1][2]);
            }
        }

        // epilogue phase 1: per-row local min -> shared atomicMin
        int cbase = nt * G2_BN + wn * 32;
        float cq[4][2];
        #pragma unroll
        for (int j = 0; j < 4; j++) {
            cq[j][0] = g_cbsq[cbase + j * 8 + tig * 2];
            cq[j][1] = g_cbsq[cbase + j * 8 + tig * 2 + 1];
        }
        float lmin[2][2] = {{3.4e38f, 3.4e38f}, {3.4e38f, 3.4e38f}};
        #pragma unroll
        for (int i = 0; i < 2; i++)
            #pragma unroll
            for (int j = 0; j < 4; j++) {
                float s00 = fmaf(-2.f, d[i][j][0], cq[j][0]);
                float s01 = fmaf(-2.f, d[i][j][1], cq[j][1]);
                float s10 = fmaf(-2.f, d[i][j][2], cq[j][0]);
                float s11 = fmaf(-2.f, d[i][j][3], cq[j][1]);
                lmin[i][0] = fminf(lmin[i][0], fminf(s00, s01));
                lmin[i][1] = fminf(lmin[i][1], fminf(s10, s11));
            }
        #pragma unroll
        for (int i = 0; i < 2; i++) {
            atomicMin(&s_rowkey[lr[i][0]], fkey(lmin[i][0]));
            atomicMin(&s_rowkey[lr[i][1]], fkey(lmin[i][1]));
        }
        __syncthreads();     // mins folded; ALL warps done reading Bs

        // issue B(nt+1) into the single buffer (safe post-barrier),
        // overlapping with the register-only phase 2 and the peer CTA
        if (nt + 1 < NT_CNT) ISSUE_B(nt + 1);
        CP_COMMIT();

        // epilogue phase 2: insert candidates vs tightened threshold
        #pragma unroll
        for (int i = 0; i < 2; i++)
            #pragma unroll
            for (int h = 0; h < 2; h++) {
                float thr = funkey(s_rowkey[lr[i][h]]) + RESCUE_DELTA;
                #pragma unroll
                for (int j = 0; j < 4; j++) {
                    float sa = fmaf(-2.f, d[i][j][h * 2 + 0], cq[j][0]);
                    float sb = fmaf(-2.f, d[i][j][h * 2 + 1], cq[j][1]);
                    int c = cbase + j * 8 + tig * 2;
                    if (sa <= thr) {
                        int pos = atomicAdd(&s_cnt[lr[i][h]], 1);
                        if (pos < CAND_MAX) s_cand[lr[i][h]][pos] = (uint16_t)c;
                    }
                    if (sb <= thr) {
                        int pos = atomicAdd(&s_cnt[lr[i][h]], 1);
                        if (pos < CAND_MAX) s_cand[lr[i][h]][pos] = (uint16_t)(c + 1);
                    }
                }
            }
    }

    __syncthreads();
    if (tid < G2_BM) {
        g_ncand[row0 + tid] = s_cnt[tid];
        #pragma unroll
        for (int i = 0; i < CAND_MAX / 8; i++)
            *(uint4*)&g_cand[row0 + tid][i * 8] = *(uint4*)&s_cand[tid][i * 8];
    }
}

// ---------------- kernel 3: exact rescue over candidates (validated R9-R12) ----------------
__global__ __launch_bounds__(256) void rescue_kernel(const float* __restrict__ X,
                                                     float* __restrict__ out) {
    int wid  = threadIdx.x >> 5;
    int lane = threadIdx.x & 31;
    int row  = blockIdx.x * 8 + wid;

    const float* xrow = X + (size_t)row * D_K;
    float x[32];
    #pragma unroll
    for (int t = 0; t < 32; t++) x[t] = xrow[lane + t * 32];

    float bestv = 3.4e38f;
    int   besti = C_N;
    int n = g_ncand[row];

    if (n <= CAND_MAX) {
        for (int i = 0; i < n; i++) {
            int c = g_cand[row][i];
            const float* urow = g_U + (size_t)c * D_K;
            float part = 0.f;
            #pragma unroll 8
            for (int t = 0; t < 32; t++)
                part = fmaf(x[t], urow[lane + t * 32], part);
            #pragma unroll
            for (int off = 16; off > 0; off >>= 1)
                part += __shfl_xor_sync(0xffffffffu, part, off);
            float sc = fmaf(-2.f, part, g_cbsq[c]);
            if (sc < bestv || (sc == bestv && c < besti)) { bestv = sc; besti = c; }
        }
    } else {
        for (int c = 0; c < C_N; c++) {
            const float* urow = g_U + (size_t)c * D_K;
            float part = 0.f;
            #pragma unroll 8
            for (int t = 0; t < 32; t++)
                part = fmaf(x[t], urow[lane + t * 32], part);
            #pragma unroll
            for (int off = 16; off > 0; off >>= 1)
                part += __shfl_xor_sync(0xffffffffu, part, off);
            float sc = fmaf(-2.f, part, g_cbsq[c]);
            if (sc < bestv) { bestv = sc; besti = c; }
        }
    }
    if (lane == 0) out[row] = (float)besti;
}

// ---------------- launch ----------------
extern "C" void kernel_launch(void* const* d_in, const int* in_sizes, int n_in,
                              void* d_out, int out_size) {
    (void)out_size;
    const float* X  = 0;
    const float* W  = 0;
    const float* CB = 0;
    for (int i = 0; i < n_in; i++) {
        long long s = (long long)in_sizes[i];
        if      (s == (long long)M_TOTAL * D_K) X  = (const float*)d_in[i];
        else if (s == (long long)Q_N * D_K)     W  = (const float*)d_in[i];
        else if (s == (long long)Q_N * C_N)     CB = (const float*)d_in[i];
    }
    if (!X)  X  = (const float*)d_in[0];
    if (!W  && n_in > 2) W  = (const float*)d_in[2];
    if (!CB && n_in > 3) CB = (const float*)d_in[3];

    float* out = (float*)d_out;

    cudaFuncSetAttribute(gemm2_tc_kernel,
                         cudaFuncAttributeMaxDynamicSharedMemorySize, G2_SMEM);

    prep_kernel<<<64 + 4096 + 256, 256>>>(CB, W);
    ugemm_kernel<<<dim3(C_N / 128, D_K / 64), 256>>>(CB, W);
    gemm1b_kernel<<<dim3(M_TOTAL / 128, Q_N / 128), 256>>>(X);
    gemm2_tc_kernel<<<M_TOTAL / G2_BM, G2_THREADS, G2_SMEM>>>();
    rescue_kernel<<<M_TOTAL / 8, 256>>>(X, out);
}